// round 1
// baseline (speedup 1.0000x reference)
#include <cuda_runtime.h>
#include <cuda_bf16.h>
#include <math.h>

// Problem constants
#define T0 512
#define T1 1536
#define TT 2048
#define WIDTH 2048
#define NH 16
#define KH 4
#define HD 128
// d_out layout (floats): out0 | out1 | cached_k | cached_v
#define OUT0_BASE 0
#define OUT1_BASE (T0*WIDTH)                    // 1048576
#define KC_BASE   ((T0+T1)*WIDTH)               // 4194304
#define VC_BASE   (KC_BASE + TT*KH*HD)          // 5242880

#define NEGV -2.3819763e38f

// Scratch (device globals; no runtime allocation)
__device__ float g_qg[TT * NH * 256];   // 32 MB: per token, per head: [q(128) | gate(128)]
__device__ float g_kraw[TT * KH * HD];  // 4 MB
__device__ float g_q[TT * NH * HD];     // 16 MB: normed+roped+scaled q
__device__ float g_enc[TT * NH * HD];   // 16 MB: attention out, gated in-place

// ---------------------------------------------------------------------------
// Batched tiled fp32 GEMM: C[(row)*ldc + batch*strideC + bn + col] =
//   sum_k A[row*lda + k] * B[batch*strideB + k*ldb + bn + col]
// BM=BN=64, BK=16, 256 threads, 4x4 microtile. All dims divisible; no bounds.
// ---------------------------------------------------------------------------
__global__ __launch_bounds__(256) void gemm_batched(
    const float* __restrict__ A, int lda,
    const float* __restrict__ B, int strideB, int ldb,
    float* __restrict__ C, int ldc, int strideC, int Kdim)
{
    const int bm = blockIdx.x * 64;
    const int bn = blockIdx.y * 64;
    const float* Bp = B + (long)blockIdx.z * strideB;
    float* Cp = C + blockIdx.z * strideC;

    __shared__ float As[64][17];
    __shared__ float Bs[16][64];

    const int tid = threadIdx.x;
    const int tx = tid & 15;
    const int ty = tid >> 4;

    float acc[4][4] = {};

    for (int k0 = 0; k0 < Kdim; k0 += 16) {
        // A tile 64x16
        #pragma unroll
        for (int p = 0; p < 4; p++) {
            int r = p * 16 + (tid >> 4);
            int c = tid & 15;
            As[r][c] = A[(bm + r) * lda + k0 + c];
        }
        // B tile 16x64
        #pragma unroll
        for (int p = 0; p < 4; p++) {
            int r = p * 4 + (tid >> 6);
            int c = tid & 63;
            Bs[r][c] = Bp[(k0 + r) * ldb + bn + c];
        }
        __syncthreads();
        #pragma unroll
        for (int kk = 0; kk < 16; kk++) {
            float a0 = As[ty * 4 + 0][kk];
            float a1 = As[ty * 4 + 1][kk];
            float a2 = As[ty * 4 + 2][kk];
            float a3 = As[ty * 4 + 3][kk];
            float4 b = *(const float4*)&Bs[kk][tx * 4];
            acc[0][0] += a0 * b.x; acc[0][1] += a0 * b.y; acc[0][2] += a0 * b.z; acc[0][3] += a0 * b.w;
            acc[1][0] += a1 * b.x; acc[1][1] += a1 * b.y; acc[1][2] += a1 * b.z; acc[1][3] += a1 * b.w;
            acc[2][0] += a2 * b.x; acc[2][1] += a2 * b.y; acc[2][2] += a2 * b.z; acc[2][3] += a2 * b.w;
            acc[3][0] += a3 * b.x; acc[3][1] += a3 * b.y; acc[3][2] += a3 * b.z; acc[3][3] += a3 * b.w;
        }
        __syncthreads();
    }
    #pragma unroll
    for (int i = 0; i < 4; i++) {
        float* dst = Cp + (bm + ty * 4 + i) * ldc + bn + tx * 4;
        dst[0] = acc[i][0]; dst[1] = acc[i][1]; dst[2] = acc[i][2]; dst[3] = acc[i][3];
    }
}

// ---------------------------------------------------------------------------
// RMSNorm + RoPE for Q (from qg), writes g_q scaled by H^-0.5.
// 1 warp per (t, n) row. 128 threads/block = 4 rows.
// ---------------------------------------------------------------------------
__global__ __launch_bounds__(128) void qnorm_rope(
    const float* __restrict__ qg, float* __restrict__ qout,
    const int* __restrict__ positions,
    const float* __restrict__ qn0, const float* __restrict__ qn1)
{
    int row  = blockIdx.x * 4 + (threadIdx.x >> 5);   // 0 .. TT*NH-1
    int lane = threadIdx.x & 31;
    int t = row >> 4;
    int n = row & 15;
    const float* src = qg + t * (NH * 256) + n * 256;

    float v0 = src[lane];
    float v1 = src[lane + 32];
    float v2 = src[lane + 64];
    float v3 = src[lane + 96];
    float ss = v0 * v0 + v1 * v1 + v2 * v2 + v3 * v3;
    #pragma unroll
    for (int o = 16; o; o >>= 1) ss += __shfl_xor_sync(0xffffffffu, ss, o);
    float inv = rsqrtf(ss * (1.0f / 128.0f) + 1e-6f);

    const float* qn = (t < T0) ? qn0 : qn1;
    v0 = v0 * inv * (1.0f + qn[lane]);
    v1 = v1 * inv * (1.0f + qn[lane + 32]);
    v2 = v2 * inv * (1.0f + qn[lane + 64]);
    v3 = v3 * inv * (1.0f + qn[lane + 96]);

    float p = (float)positions[t];
    float freq = powf(1000000.0f, -(float)lane / 32.0f);
    float ang = p * freq;
    float s, c;
    sincosf(ang, &s, &c);

    const float SCL = 0.08838834764831845f;  // 128^-0.5
    float* dst = qout + t * (NH * HD) + n * HD;
    dst[lane]      = (v0 * c - v1 * s) * SCL;
    dst[lane + 32] = (v1 * c + v0 * s) * SCL;
    dst[lane + 64] = v2 * SCL;
    dst[lane + 96] = v3 * SCL;
}

// RMSNorm + RoPE for K (from kraw), writes cached_k region of d_out.
__global__ __launch_bounds__(128) void knorm_rope(
    const float* __restrict__ kraw, float* __restrict__ kcache,
    const int* __restrict__ positions,
    const float* __restrict__ kn0, const float* __restrict__ kn1)
{
    int row  = blockIdx.x * 4 + (threadIdx.x >> 5);   // 0 .. TT*KH-1
    int lane = threadIdx.x & 31;
    int t  = row >> 2;
    int kk = row & 3;
    const float* src = kraw + t * (KH * HD) + kk * HD;

    float v0 = src[lane];
    float v1 = src[lane + 32];
    float v2 = src[lane + 64];
    float v3 = src[lane + 96];
    float ss = v0 * v0 + v1 * v1 + v2 * v2 + v3 * v3;
    #pragma unroll
    for (int o = 16; o; o >>= 1) ss += __shfl_xor_sync(0xffffffffu, ss, o);
    float inv = rsqrtf(ss * (1.0f / 128.0f) + 1e-6f);

    const float* kn = (t < T0) ? kn0 : kn1;
    v0 = v0 * inv * (1.0f + kn[lane]);
    v1 = v1 * inv * (1.0f + kn[lane + 32]);
    v2 = v2 * inv * (1.0f + kn[lane + 64]);
    v3 = v3 * inv * (1.0f + kn[lane + 96]);

    float p = (float)positions[t];
    float freq = powf(1000000.0f, -(float)lane / 32.0f);
    float ang = p * freq;
    float s, c;
    sincosf(ang, &s, &c);

    float* dst = kcache + t * (KH * HD) + kk * HD;
    dst[lane]      = v0 * c - v1 * s;
    dst[lane + 32] = v1 * c + v0 * s;
    dst[lane + 64] = v2;
    dst[lane + 96] = v3;
}

// ---------------------------------------------------------------------------
// Flash-style causal attention. Block = (64-query tile, head). 256 threads.
// Dynamic smem: Qs[64][132] | Ks[128][68] (union Vs[64][128]) | Ss[64][65]
// ---------------------------------------------------------------------------
#define QS_STR 132
#define KS_STR 68
#define SS_STR 65
#define SMEM_FLOATS (64*QS_STR + 128*KS_STR + 64*SS_STR)

__global__ __launch_bounds__(256) void attn_kernel(
    const float* __restrict__ q, const float* __restrict__ kc,
    const float* __restrict__ vc, float* __restrict__ enc)
{
    extern __shared__ float sm[];
    float* Qs = sm;                       // [64][132]
    float* Ks = sm + 64 * QS_STR;         // [128][68], transposed K (c, s)
    float* Vs = Ks;                       // union: [64][128]
    float* Ss = Ks + 128 * KS_STR;        // [64][65]
    __shared__ float m_s[64], l_s[64], a_s[64];

    const int tid = threadIdx.x;
    const int tx = tid & 15;
    const int ty = tid >> 4;
    const int qt = blockIdx.x;
    const int n  = blockIdx.y;
    const int kvh = n >> 2;
    const int qbase = qt * 64;

    for (int idx = tid; idx < 64 * 128; idx += 256) {
        int r = idx >> 7, h = idx & 127;
        Qs[r * QS_STR + h] = q[(qbase + r) * (NH * HD) + n * HD + h];
    }
    if (tid < 64) { m_s[tid] = -3.0e38f; l_s[tid] = 0.0f; }

    float acc[4][8] = {};

    for (int j = 0; j <= qt; j++) {
        __syncthreads();  // covers Q/stat init & protects Vs from prev iter
        const int sb = j * 64;
        for (int idx = tid; idx < 64 * 128; idx += 256) {
            int s = idx >> 7, c = idx & 127;
            Ks[c * KS_STR + s] = kc[(sb + s) * (KH * HD) + kvh * HD + c];
        }
        __syncthreads();

        // S = Q K^T  (64x64), 4x4 per thread
        float sa[4][4] = {};
        #pragma unroll 4
        for (int c = 0; c < 128; c++) {
            float a0 = Qs[(ty * 4 + 0) * QS_STR + c];
            float a1 = Qs[(ty * 4 + 1) * QS_STR + c];
            float a2 = Qs[(ty * 4 + 2) * QS_STR + c];
            float a3 = Qs[(ty * 4 + 3) * QS_STR + c];
            float4 b = *(const float4*)&Ks[c * KS_STR + tx * 4];
            sa[0][0] += a0 * b.x; sa[0][1] += a0 * b.y; sa[0][2] += a0 * b.z; sa[0][3] += a0 * b.w;
            sa[1][0] += a1 * b.x; sa[1][1] += a1 * b.y; sa[1][2] += a1 * b.z; sa[1][3] += a1 * b.w;
            sa[2][0] += a2 * b.x; sa[2][1] += a2 * b.y; sa[2][2] += a2 * b.z; sa[2][3] += a2 * b.w;
            sa[3][0] += a3 * b.x; sa[3][1] += a3 * b.y; sa[3][2] += a3 * b.z; sa[3][3] += a3 * b.w;
        }
        const bool diag = (j == qt);
        #pragma unroll
        for (int i = 0; i < 4; i++) {
            int r = ty * 4 + i;
            #pragma unroll
            for (int jj = 0; jj < 4; jj++) {
                int cc = tx * 4 + jj;
                float val = sa[i][jj];
                if (diag && cc > r) val = NEGV;
                Ss[r * SS_STR + cc] = val;
            }
        }
        __syncthreads();

        // online softmax per row
        if (tid < 64) {
            int r = tid;
            float mold = m_s[r];
            float rmax = -3.0e38f;
            for (int c = 0; c < 64; c++) rmax = fmaxf(rmax, Ss[r * SS_STR + c]);
            float mn = fmaxf(mold, rmax);
            float al = expf(mold - mn);
            float sum = 0.0f;
            for (int c = 0; c < 64; c++) {
                float pv = expf(Ss[r * SS_STR + c] - mn);
                Ss[r * SS_STR + c] = pv;
                sum += pv;
            }
            l_s[r] = l_s[r] * al + sum;
            m_s[r] = mn;
            a_s[r] = al;
        }
        __syncthreads();

        // load V (overwrites Ks region)
        for (int idx = tid; idx < 64 * 128; idx += 256) {
            int s = idx >> 7, c = idx & 127;
            Vs[s * 128 + c] = vc[(sb + s) * (KH * HD) + kvh * HD + c];
        }
        __syncthreads();

        // rescale + P V
        float al0 = a_s[ty * 4 + 0], al1 = a_s[ty * 4 + 1];
        float al2 = a_s[ty * 4 + 2], al3 = a_s[ty * 4 + 3];
        #pragma unroll
        for (int jj = 0; jj < 8; jj++) {
            acc[0][jj] *= al0; acc[1][jj] *= al1; acc[2][jj] *= al2; acc[3][jj] *= al3;
        }
        #pragma unroll 2
        for (int c = 0; c < 64; c++) {
            float p0 = Ss[(ty * 4 + 0) * SS_STR + c];
            float p1 = Ss[(ty * 4 + 1) * SS_STR + c];
            float p2 = Ss[(ty * 4 + 2) * SS_STR + c];
            float p3 = Ss[(ty * 4 + 3) * SS_STR + c];
            float4 va = *(const float4*)&Vs[c * 128 + tx * 8];
            float4 vb = *(const float4*)&Vs[c * 128 + tx * 8 + 4];
            acc[0][0] += p0 * va.x; acc[0][1] += p0 * va.y; acc[0][2] += p0 * va.z; acc[0][3] += p0 * va.w;
            acc[0][4] += p0 * vb.x; acc[0][5] += p0 * vb.y; acc[0][6] += p0 * vb.z; acc[0][7] += p0 * vb.w;
            acc[1][0] += p1 * va.x; acc[1][1] += p1 * va.y; acc[1][2] += p1 * va.z; acc[1][3] += p1 * va.w;
            acc[1][4] += p1 * vb.x; acc[1][5] += p1 * vb.y; acc[1][6] += p1 * vb.z; acc[1][7] += p1 * vb.w;
            acc[2][0] += p2 * va.x; acc[2][1] += p2 * va.y; acc[2][2] += p2 * va.z; acc[2][3] += p2 * va.w;
            acc[2][4] += p2 * vb.x; acc[2][5] += p2 * vb.y; acc[2][6] += p2 * vb.z; acc[2][7] += p2 * vb.w;
            acc[3][0] += p3 * va.x; acc[3][1] += p3 * va.y; acc[3][2] += p3 * va.z; acc[3][3] += p3 * va.w;
            acc[3][4] += p3 * vb.x; acc[3][5] += p3 * vb.y; acc[3][6] += p3 * vb.z; acc[3][7] += p3 * vb.w;
        }
    }

    #pragma unroll
    for (int i = 0; i < 4; i++) {
        int r = ty * 4 + i;
        float invl = 1.0f / l_s[r];
        float* dst = enc + (qbase + r) * (NH * HD) + n * HD + tx * 8;
        #pragma unroll
        for (int jj = 0; jj < 8; jj++) dst[jj] = acc[i][jj] * invl;
    }
}

// enc *= sigmoid(gate)
__global__ __launch_bounds__(256) void gate_kernel(
    const float* __restrict__ qg, float* __restrict__ enc)
{
    int idx = blockIdx.x * 256 + threadIdx.x;   // over TT * NH * HD
    int t = idx >> 11;
    int rem = idx & 2047;
    int n = rem >> 7;
    int h = rem & 127;
    float g = qg[t * (NH * 256) + n * 256 + 128 + h];
    enc[idx] *= 1.0f / (1.0f + expf(-g));
}

// ---------------------------------------------------------------------------
extern "C" void kernel_launch(void* const* d_in, const int* in_sizes, int n_in,
                              void* d_out, int out_size)
{
    const float* x0    = (const float*)d_in[0];
    const float* x1    = (const float*)d_in[1];
    const int*   pos   = (const int*)d_in[2];
    // d_in[3] = attn_mask (causal tril; handled analytically)
    const float* qg_w0 = (const float*)d_in[4];
    const float* k_w0  = (const float*)d_in[5];
    const float* v_w0  = (const float*)d_in[6];
    const float* qn0   = (const float*)d_in[7];
    const float* kn0   = (const float*)d_in[8];
    const float* o_w0  = (const float*)d_in[9];
    const float* qg_w1 = (const float*)d_in[10];
    const float* k_w1  = (const float*)d_in[11];
    const float* v_w1  = (const float*)d_in[12];
    const float* qn1   = (const float*)d_in[13];
    const float* kn1   = (const float*)d_in[14];
    const float* o_w1  = (const float*)d_in[15];

    float* out = (float*)d_out;

    float *qg, *kraw, *q, *enc;
    cudaGetSymbolAddress((void**)&qg,   g_qg);
    cudaGetSymbolAddress((void**)&kraw, g_kraw);
    cudaGetSymbolAddress((void**)&q,    g_q);
    cudaGetSymbolAddress((void**)&enc,  g_enc);

    // --- projections (stream 0: T0=512 rows; stream 1: T1=1536 rows) ---
    gemm_batched<<<dim3(T0/64, 4, NH), 256>>>(x0, WIDTH, qg_w0, WIDTH*256, 256,
                                              qg, NH*256, 256, WIDTH);
    gemm_batched<<<dim3(T1/64, 4, NH), 256>>>(x1, WIDTH, qg_w1, WIDTH*256, 256,
                                              qg + T0*NH*256, NH*256, 256, WIDTH);
    gemm_batched<<<dim3(T0/64, 2, KH), 256>>>(x0, WIDTH, k_w0, WIDTH*HD, HD,
                                              kraw, KH*HD, HD, WIDTH);
    gemm_batched<<<dim3(T1/64, 2, KH), 256>>>(x1, WIDTH, k_w1, WIDTH*HD, HD,
                                              kraw + T0*KH*HD, KH*HD, HD, WIDTH);
    gemm_batched<<<dim3(T0/64, 2, KH), 256>>>(x0, WIDTH, v_w0, WIDTH*HD, HD,
                                              out + VC_BASE, KH*HD, HD, WIDTH);
    gemm_batched<<<dim3(T1/64, 2, KH), 256>>>(x1, WIDTH, v_w1, WIDTH*HD, HD,
                                              out + VC_BASE + T0*KH*HD, KH*HD, HD, WIDTH);

    // --- norms + rope ---
    qnorm_rope<<<TT*NH/4, 128>>>(qg, q, pos, qn0, qn1);
    knorm_rope<<<TT*KH/4, 128>>>(kraw, out + KC_BASE, pos, kn0, kn1);

    // --- attention ---
    cudaFuncSetAttribute(attn_kernel, cudaFuncAttributeMaxDynamicSharedMemorySize,
                         SMEM_FLOATS * sizeof(float));
    attn_kernel<<<dim3(TT/64, NH), 256, SMEM_FLOATS * sizeof(float)>>>(
        q, out + KC_BASE, out + VC_BASE, enc);

    // --- gate + output projection ---
    gate_kernel<<<TT*NH*HD/256, 256>>>(qg, enc);
    gemm_batched<<<dim3(T0/64, WIDTH/64, 1), 256>>>(enc, NH*HD, o_w0, 0, WIDTH,
                                                    out + OUT0_BASE, WIDTH, 0, NH*HD);
    gemm_batched<<<dim3(T1/64, WIDTH/64, 1), 256>>>(enc + T0*NH*HD, NH*HD, o_w1, 0, WIDTH,
                                                    out + OUT1_BASE, WIDTH, 0, NH*HD);
}

// round 2
// speedup vs baseline: 1.3970x; 1.3970x over previous
#include <cuda_runtime.h>
#include <cuda_bf16.h>
#include <math.h>

// Problem constants
#define T0 512
#define T1 1536
#define TT 2048
#define WIDTH 2048
#define NH 16
#define KH 4
#define HD 128
// d_out layout (floats): out0 | out1 | cached_k | cached_v
#define KC_BASE   ((T0+T1)*WIDTH)               // 4194304
#define VC_BASE   (KC_BASE + TT*KH*HD)          // 5242880

#define NEGV -2.3819763e38f

// Scratch (device globals; no runtime allocation)
__device__ float g_qg[TT * NH * 256];   // per token, per head: [q(128) | gate(128)]
__device__ float g_kraw[TT * KH * HD];
__device__ float g_q[TT * NH * HD];     // normed+roped+scaled q
__device__ float g_enc[TT * NH * HD];   // attention out, gated in-place

// ---------------------------------------------------------------------------
// SGEMM core: 128x128 tile, BK=8, 256 threads, 8x8 microtile, double-buffered.
// Caller passes A,B,C already offset to the tile origin. All dims divisible.
// ---------------------------------------------------------------------------
__device__ __forceinline__ void sgemm_core(
    const float* __restrict__ A, int lda,
    const float* __restrict__ B, int ldb,
    float* __restrict__ C, int ldc, int Kdim,
    float (*As)[8][128], float (*Bs)[8][128])
{
    const int tid = threadIdx.x;
    const int arow = tid >> 1;           // 0..127
    const int acol = (tid & 1) * 4;      // 0 or 4
    const int brow = tid >> 5;           // 0..7
    const int bcol = (tid & 31) * 4;     // 0..124
    const int tx = tid & 15;
    const int ty = tid >> 4;

    const float* Aptr = A + arow * lda + acol;
    const float* Bptr = B + brow * ldb + bcol;

    // prefetch tile 0
    float4 ar = *(const float4*)Aptr;
    float4 br = *(const float4*)Bptr;
    As[0][acol + 0][arow] = ar.x;
    As[0][acol + 1][arow] = ar.y;
    As[0][acol + 2][arow] = ar.z;
    As[0][acol + 3][arow] = ar.w;
    *(float4*)&Bs[0][brow][bcol] = br;
    __syncthreads();

    float acc[8][8] = {};
    const int ntiles = Kdim / 8;

    for (int kt = 0; kt < ntiles; kt++) {
        const int cur = kt & 1;
        if (kt + 1 < ntiles) {
            ar = *(const float4*)(Aptr + (kt + 1) * 8);
            br = *(const float4*)(Bptr + (kt + 1) * 8 * ldb);
        }
        #pragma unroll
        for (int kk = 0; kk < 8; kk++) {
            float a[8], b[8];
            *(float4*)&a[0] = *(const float4*)&As[cur][kk][ty * 4];
            *(float4*)&a[4] = *(const float4*)&As[cur][kk][ty * 4 + 64];
            *(float4*)&b[0] = *(const float4*)&Bs[cur][kk][tx * 4];
            *(float4*)&b[4] = *(const float4*)&Bs[cur][kk][tx * 4 + 64];
            #pragma unroll
            for (int i = 0; i < 8; i++)
                #pragma unroll
                for (int j = 0; j < 8; j++)
                    acc[i][j] += a[i] * b[j];
        }
        if (kt + 1 < ntiles) {
            const int nxt = cur ^ 1;
            As[nxt][acol + 0][arow] = ar.x;
            As[nxt][acol + 1][arow] = ar.y;
            As[nxt][acol + 2][arow] = ar.z;
            As[nxt][acol + 3][arow] = ar.w;
            *(float4*)&Bs[nxt][brow][bcol] = br;
        }
        __syncthreads();
    }

    #pragma unroll
    for (int i = 0; i < 8; i++) {
        int r = (i < 4) ? (ty * 4 + i) : (ty * 4 + 64 + (i - 4));
        *(float4*)&C[r * ldc + tx * 4] =
            make_float4(acc[i][0], acc[i][1], acc[i][2], acc[i][3]);
        *(float4*)&C[r * ldc + tx * 4 + 64] =
            make_float4(acc[i][4], acc[i][5], acc[i][6], acc[i][7]);
    }
}

// qg projection, both streams fused: grid (16, 2, 16)
__global__ __launch_bounds__(256, 2) void proj_qg_kernel(
    const float* __restrict__ x0, const float* __restrict__ x1,
    const float* __restrict__ w0, const float* __restrict__ w1,
    float* __restrict__ qg)
{
    __shared__ float As[2][8][128];
    __shared__ float Bs[2][8][128];
    const int tile = blockIdx.x;
    const int bn = blockIdx.y * 128;
    const int n = blockIdx.z;
    const float* A = (tile < 4) ? (x0 + (long)tile * 128 * WIDTH)
                                : (x1 + (long)(tile - 4) * 128 * WIDTH);
    const float* B = ((tile < 4) ? w0 : w1) + (long)n * WIDTH * 256 + bn;
    float* C = qg + (long)tile * 128 * (NH * 256) + n * 256 + bn;
    sgemm_core(A, WIDTH, B, 256, C, NH * 256, WIDTH, As, Bs);
}

// K+V projections, both streams fused: grid (16, 1, 8). z<4: K->kraw, z>=4: V->vcache
__global__ __launch_bounds__(256, 2) void proj_kv_kernel(
    const float* __restrict__ x0, const float* __restrict__ x1,
    const float* __restrict__ kw0, const float* __restrict__ kw1,
    const float* __restrict__ vw0, const float* __restrict__ vw1,
    float* __restrict__ kraw, float* __restrict__ vcache)
{
    __shared__ float As[2][8][128];
    __shared__ float Bs[2][8][128];
    const int tile = blockIdx.x;
    const int z = blockIdx.z;
    const bool isV = (z >= 4);
    const int kk = z & 3;
    const float* A = (tile < 4) ? (x0 + (long)tile * 128 * WIDTH)
                                : (x1 + (long)(tile - 4) * 128 * WIDTH);
    const float* W = isV ? ((tile < 4) ? vw0 : vw1) : ((tile < 4) ? kw0 : kw1);
    const float* B = W + (long)kk * WIDTH * HD;
    float* Cb = isV ? vcache : kraw;
    float* C = Cb + (long)tile * 128 * (KH * HD) + kk * HD;
    sgemm_core(A, WIDTH, B, HD, C, KH * HD, WIDTH, As, Bs);
}

// output projection, both streams fused: grid (16, 16)
__global__ __launch_bounds__(256, 2) void proj_out_kernel(
    const float* __restrict__ enc,
    const float* __restrict__ ow0, const float* __restrict__ ow1,
    float* __restrict__ out)
{
    __shared__ float As[2][8][128];
    __shared__ float Bs[2][8][128];
    const int tile = blockIdx.x;
    const int bn = blockIdx.y * 128;
    const float* A = enc + (long)tile * 128 * (NH * HD);
    const float* B = ((tile < 4) ? ow0 : ow1) + bn;
    float* C = out + (long)tile * 128 * WIDTH + bn;
    sgemm_core(A, NH * HD, B, WIDTH, C, WIDTH, NH * HD, As, Bs);
}

// ---------------------------------------------------------------------------
// RMSNorm + RoPE for Q (from qg), writes g_q scaled by H^-0.5.
// ---------------------------------------------------------------------------
__global__ __launch_bounds__(128) void qnorm_rope(
    const float* __restrict__ qg, float* __restrict__ qout,
    const int* __restrict__ positions,
    const float* __restrict__ qn0, const float* __restrict__ qn1)
{
    int row  = blockIdx.x * 4 + (threadIdx.x >> 5);   // 0 .. TT*NH-1
    int lane = threadIdx.x & 31;
    int t = row >> 4;
    int n = row & 15;
    const float* src = qg + t * (NH * 256) + n * 256;

    float v0 = src[lane];
    float v1 = src[lane + 32];
    float v2 = src[lane + 64];
    float v3 = src[lane + 96];
    float ss = v0 * v0 + v1 * v1 + v2 * v2 + v3 * v3;
    #pragma unroll
    for (int o = 16; o; o >>= 1) ss += __shfl_xor_sync(0xffffffffu, ss, o);
    float inv = rsqrtf(ss * (1.0f / 128.0f) + 1e-6f);

    const float* qn = (t < T0) ? qn0 : qn1;
    v0 = v0 * inv * (1.0f + qn[lane]);
    v1 = v1 * inv * (1.0f + qn[lane + 32]);
    v2 = v2 * inv * (1.0f + qn[lane + 64]);
    v3 = v3 * inv * (1.0f + qn[lane + 96]);

    float p = (float)positions[t];
    float freq = powf(1000000.0f, -(float)lane / 32.0f);
    float s, c;
    sincosf(p * freq, &s, &c);

    const float SCL = 0.08838834764831845f;  // 128^-0.5
    float* dst = qout + t * (NH * HD) + n * HD;
    dst[lane]      = (v0 * c - v1 * s) * SCL;
    dst[lane + 32] = (v1 * c + v0 * s) * SCL;
    dst[lane + 64] = v2 * SCL;
    dst[lane + 96] = v3 * SCL;
}

// RMSNorm + RoPE for K (from kraw), writes cached_k region of d_out.
__global__ __launch_bounds__(128) void knorm_rope(
    const float* __restrict__ kraw, float* __restrict__ kcache,
    const int* __restrict__ positions,
    const float* __restrict__ kn0, const float* __restrict__ kn1)
{
    int row  = blockIdx.x * 4 + (threadIdx.x >> 5);   // 0 .. TT*KH-1
    int lane = threadIdx.x & 31;
    int t  = row >> 2;
    int kk = row & 3;
    const float* src = kraw + t * (KH * HD) + kk * HD;

    float v0 = src[lane];
    float v1 = src[lane + 32];
    float v2 = src[lane + 64];
    float v3 = src[lane + 96];
    float ss = v0 * v0 + v1 * v1 + v2 * v2 + v3 * v3;
    #pragma unroll
    for (int o = 16; o; o >>= 1) ss += __shfl_xor_sync(0xffffffffu, ss, o);
    float inv = rsqrtf(ss * (1.0f / 128.0f) + 1e-6f);

    const float* kn = (t < T0) ? kn0 : kn1;
    v0 = v0 * inv * (1.0f + kn[lane]);
    v1 = v1 * inv * (1.0f + kn[lane + 32]);
    v2 = v2 * inv * (1.0f + kn[lane + 64]);
    v3 = v3 * inv * (1.0f + kn[lane + 96]);

    float p = (float)positions[t];
    float freq = powf(1000000.0f, -(float)lane / 32.0f);
    float s, c;
    sincosf(p * freq, &s, &c);

    float* dst = kcache + t * (KH * HD) + kk * HD;
    dst[lane]      = v0 * c - v1 * s;
    dst[lane + 32] = v1 * c + v0 * s;
    dst[lane + 64] = v2;
    dst[lane + 96] = v3;
}

// ---------------------------------------------------------------------------
// Flash-style causal attention. Block = (64-query tile, head). 256 threads.
// ---------------------------------------------------------------------------
#define QS_STR 132
#define KS_STR 68
#define SS_STR 65
#define SMEM_FLOATS (64*QS_STR + 128*KS_STR + 64*SS_STR)

__global__ __launch_bounds__(256) void attn_kernel(
    const float* __restrict__ q, const float* __restrict__ kc,
    const float* __restrict__ vc, float* __restrict__ enc)
{
    extern __shared__ float sm[];
    float* Qs = sm;                       // [64][132]
    float* Ks = sm + 64 * QS_STR;         // [128][68], transposed K (c, s)
    float* Vs = Ks;                       // union: [64][128]
    float* Ss = Ks + 128 * KS_STR;        // [64][65]
    __shared__ float m_s[64], l_s[64], a_s[64];

    const int tid = threadIdx.x;
    const int tx = tid & 15;
    const int ty = tid >> 4;
    const int qt = blockIdx.x;
    const int n  = blockIdx.y;
    const int kvh = n >> 2;
    const int qbase = qt * 64;

    for (int idx = tid; idx < 64 * 128; idx += 256) {
        int r = idx >> 7, h = idx & 127;
        Qs[r * QS_STR + h] = q[(qbase + r) * (NH * HD) + n * HD + h];
    }
    if (tid < 64) { m_s[tid] = -3.0e38f; l_s[tid] = 0.0f; }

    float acc[4][8] = {};

    for (int j = 0; j <= qt; j++) {
        __syncthreads();
        const int sb = j * 64;
        for (int idx = tid; idx < 64 * 128; idx += 256) {
            int s = idx >> 7, c = idx & 127;
            Ks[c * KS_STR + s] = kc[(sb + s) * (KH * HD) + kvh * HD + c];
        }
        __syncthreads();

        // S = Q K^T (64x64), 4x4 per thread
        float sa[4][4] = {};
        #pragma unroll 4
        for (int c = 0; c < 128; c++) {
            float a0 = Qs[(ty * 4 + 0) * QS_STR + c];
            float a1 = Qs[(ty * 4 + 1) * QS_STR + c];
            float a2 = Qs[(ty * 4 + 2) * QS_STR + c];
            float a3 = Qs[(ty * 4 + 3) * QS_STR + c];
            float4 b = *(const float4*)&Ks[c * KS_STR + tx * 4];
            sa[0][0] += a0 * b.x; sa[0][1] += a0 * b.y; sa[0][2] += a0 * b.z; sa[0][3] += a0 * b.w;
            sa[1][0] += a1 * b.x; sa[1][1] += a1 * b.y; sa[1][2] += a1 * b.z; sa[1][3] += a1 * b.w;
            sa[2][0] += a2 * b.x; sa[2][1] += a2 * b.y; sa[2][2] += a2 * b.z; sa[2][3] += a2 * b.w;
            sa[3][0] += a3 * b.x; sa[3][1] += a3 * b.y; sa[3][2] += a3 * b.z; sa[3][3] += a3 * b.w;
        }
        const bool diag = (j == qt);
        #pragma unroll
        for (int i = 0; i < 4; i++) {
            int r = ty * 4 + i;
            #pragma unroll
            for (int jj = 0; jj < 4; jj++) {
                int cc = tx * 4 + jj;
                float val = sa[i][jj];
                if (diag && cc > r) val = NEGV;
                Ss[r * SS_STR + cc] = val;
            }
        }
        __syncthreads();

        // online softmax: 4 threads per row, 16 cols each
        {
            int r = tid >> 2;
            int qq = tid & 3;
            float* row = Ss + r * SS_STR + qq * 16;
            float mold = m_s[r];
            float rmax = -3.0e38f;
            #pragma unroll
            for (int c = 0; c < 16; c++) rmax = fmaxf(rmax, row[c]);
            rmax = fmaxf(rmax, __shfl_xor_sync(0xffffffffu, rmax, 1));
            rmax = fmaxf(rmax, __shfl_xor_sync(0xffffffffu, rmax, 2));
            float mn = fmaxf(mold, rmax);
            float sum = 0.0f;
            #pragma unroll
            for (int c = 0; c < 16; c++) {
                float pv = __expf(row[c] - mn);
                row[c] = pv;
                sum += pv;
            }
            sum += __shfl_xor_sync(0xffffffffu, sum, 1);
            sum += __shfl_xor_sync(0xffffffffu, sum, 2);
            if (qq == 0) {
                float al = __expf(mold - mn);
                l_s[r] = l_s[r] * al + sum;
                m_s[r] = mn;
                a_s[r] = al;
            }
        }
        __syncthreads();

        // load V (overwrites Ks region)
        for (int idx = tid; idx < 64 * 128; idx += 256) {
            int s = idx >> 7, c = idx & 127;
            Vs[s * 128 + c] = vc[(sb + s) * (KH * HD) + kvh * HD + c];
        }
        __syncthreads();

        // rescale + P V
        float al0 = a_s[ty * 4 + 0], al1 = a_s[ty * 4 + 1];
        float al2 = a_s[ty * 4 + 2], al3 = a_s[ty * 4 + 3];
        #pragma unroll
        for (int jj = 0; jj < 8; jj++) {
            acc[0][jj] *= al0; acc[1][jj] *= al1; acc[2][jj] *= al2; acc[3][jj] *= al3;
        }
        #pragma unroll 2
        for (int c = 0; c < 64; c++) {
            float p0 = Ss[(ty * 4 + 0) * SS_STR + c];
            float p1 = Ss[(ty * 4 + 1) * SS_STR + c];
            float p2 = Ss[(ty * 4 + 2) * SS_STR + c];
            float p3 = Ss[(ty * 4 + 3) * SS_STR + c];
            float4 va = *(const float4*)&Vs[c * 128 + tx * 8];
            float4 vb = *(const float4*)&Vs[c * 128 + tx * 8 + 4];
            acc[0][0] += p0 * va.x; acc[0][1] += p0 * va.y; acc[0][2] += p0 * va.z; acc[0][3] += p0 * va.w;
            acc[0][4] += p0 * vb.x; acc[0][5] += p0 * vb.y; acc[0][6] += p0 * vb.z; acc[0][7] += p0 * vb.w;
            acc[1][0] += p1 * va.x; acc[1][1] += p1 * va.y; acc[1][2] += p1 * va.z; acc[1][3] += p1 * va.w;
            acc[1][4] += p1 * vb.x; acc[1][5] += p1 * vb.y; acc[1][6] += p1 * vb.z; acc[1][7] += p1 * vb.w;
            acc[2][0] += p2 * va.x; acc[2][1] += p2 * va.y; acc[2][2] += p2 * va.z; acc[2][3] += p2 * va.w;
            acc[2][4] += p2 * vb.x; acc[2][5] += p2 * vb.y; acc[2][6] += p2 * vb.z; acc[2][7] += p2 * vb.w;
            acc[3][0] += p3 * va.x; acc[3][1] += p3 * va.y; acc[3][2] += p3 * va.z; acc[3][3] += p3 * va.w;
            acc[3][4] += p3 * vb.x; acc[3][5] += p3 * vb.y; acc[3][6] += p3 * vb.z; acc[3][7] += p3 * vb.w;
        }
    }

    #pragma unroll
    for (int i = 0; i < 4; i++) {
        int r = ty * 4 + i;
        float invl = 1.0f / l_s[r];
        float* dst = enc + (qbase + r) * (NH * HD) + n * HD + tx * 8;
        #pragma unroll
        for (int jj = 0; jj < 8; jj++) dst[jj] = acc[i][jj] * invl;
    }
}

// enc *= sigmoid(gate)
__global__ __launch_bounds__(256) void gate_kernel(
    const float* __restrict__ qg, float* __restrict__ enc)
{
    int idx = blockIdx.x * 256 + threadIdx.x;   // over TT * NH * HD
    int t = idx >> 11;
    int rem = idx & 2047;
    int n = rem >> 7;
    int h = rem & 127;
    float g = qg[t * (NH * 256) + n * 256 + 128 + h];
    enc[idx] *= 1.0f / (1.0f + __expf(-g));
}

// ---------------------------------------------------------------------------
extern "C" void kernel_launch(void* const* d_in, const int* in_sizes, int n_in,
                              void* d_out, int out_size)
{
    const float* x0    = (const float*)d_in[0];
    const float* x1    = (const float*)d_in[1];
    const int*   pos   = (const int*)d_in[2];
    // d_in[3] = attn_mask (causal tril; handled analytically)
    const float* qg_w0 = (const float*)d_in[4];
    const float* k_w0  = (const float*)d_in[5];
    const float* v_w0  = (const float*)d_in[6];
    const float* qn0   = (const float*)d_in[7];
    const float* kn0   = (const float*)d_in[8];
    const float* o_w0  = (const float*)d_in[9];
    const float* qg_w1 = (const float*)d_in[10];
    const float* k_w1  = (const float*)d_in[11];
    const float* v_w1  = (const float*)d_in[12];
    const float* qn1   = (const float*)d_in[13];
    const float* kn1   = (const float*)d_in[14];
    const float* o_w1  = (const float*)d_in[15];

    float* out = (float*)d_out;

    float *qg, *kraw, *q, *enc;
    cudaGetSymbolAddress((void**)&qg,   g_qg);
    cudaGetSymbolAddress((void**)&kraw, g_kraw);
    cudaGetSymbolAddress((void**)&q,    g_q);
    cudaGetSymbolAddress((void**)&enc,  g_enc);

    // --- projections (fused across streams) ---
    proj_qg_kernel<<<dim3(16, 2, 16), 256>>>(x0, x1, qg_w0, qg_w1, qg);
    proj_kv_kernel<<<dim3(16, 1, 8), 256>>>(x0, x1, k_w0, k_w1, v_w0, v_w1,
                                            kraw, out + VC_BASE);

    // --- norms + rope ---
    qnorm_rope<<<TT*NH/4, 128>>>(qg, q, pos, qn0, qn1);
    knorm_rope<<<TT*KH/4, 128>>>(kraw, out + KC_BASE, pos, kn0, kn1);

    // --- attention ---
    cudaFuncSetAttribute(attn_kernel, cudaFuncAttributeMaxDynamicSharedMemorySize,
                         SMEM_FLOATS * sizeof(float));
    attn_kernel<<<dim3(TT/64, NH), 256, SMEM_FLOATS * sizeof(float)>>>(
        q, out + KC_BASE, out + VC_BASE, enc);

    // --- gate + output projection (out0|out1 contiguous in d_out) ---
    gate_kernel<<<TT*NH*HD/256, 256>>>(qg, enc);
    proj_out_kernel<<<dim3(16, 16), 256>>>(enc, o_w0, o_w1, out);
}

// round 3
// speedup vs baseline: 3.0439x; 2.1789x over previous
#include <cuda_runtime.h>
#include <cuda_bf16.h>
#include <math.h>
#include <stdint.h>

// Problem constants
#define T0 512
#define TT 2048
#define WIDTH 2048
#define NH 16
#define KH 4
#define HD 128
#define KC_BASE (TT*WIDTH)
#define VC_BASE (KC_BASE + TT*KH*HD)
#define NEGV -2.3819763e38f

// Scratch
__device__ float g_qg[TT * NH * 256];
__device__ float g_kraw[TT * KH * HD];
__device__ float g_q[TT * NH * HD];
__device__ float g_enc[TT * NH * HD];

// ---------------------------------------------------------------------------
// tf32 helpers
// ---------------------------------------------------------------------------
__device__ __forceinline__ uint32_t f2tf(float f) {
    uint32_t r;
    asm("cvt.rna.tf32.f32 %0, %1;" : "=r"(r) : "f"(f));
    return r;
}

// m16n8k8 tf32 MMA, fp32 accumulate. a: 4 regs, b: 2 regs, c: 4 floats.
__device__ __forceinline__ void mma8(float* c, const uint32_t* a, const uint32_t* b) {
    asm volatile(
        "mma.sync.aligned.m16n8k8.row.col.f32.tf32.tf32.f32 "
        "{%0,%1,%2,%3},{%4,%5,%6,%7},{%8,%9},{%0,%1,%2,%3};"
        : "+f"(c[0]), "+f"(c[1]), "+f"(c[2]), "+f"(c[3])
        : "r"(a[0]), "r"(a[1]), "r"(a[2]), "r"(a[3]), "r"(b[0]), "r"(b[1]));
}

// ---------------------------------------------------------------------------
// MMA GEMM core: 128x128 block tile, BK=16, 256 threads (8 warps, 32x64 warp
// tile), double-buffered smem, tf32 fragments, fp32 accum. Kdim % 16 == 0.
// A row-major [m][k], B row-major [k][n], C row-major.
// ---------------------------------------------------------------------------
#define ASTR 17
#define BSTR 136

__device__ __forceinline__ void mma_gemm_core(
    const float* __restrict__ A, int lda,
    const float* __restrict__ B, int ldb,
    float* __restrict__ C, int ldc, int Kdim,
    uint32_t* As, uint32_t* Bs)   // As: 2*128*ASTR, Bs: 2*16*BSTR
{
    const int tid = threadIdx.x;
    const int lane = tid & 31;
    const int g = lane >> 2;         // 0..7
    const int t = lane & 3;          // 0..3
    const int wid = tid >> 5;
    const int mw = (wid >> 1) * 32;  // warp M base
    const int nw = (wid & 1) * 64;   // warp N base

    // loader indices
    const int ra = tid >> 1;               // A row 0..127
    const int ca = (tid & 1) * 8;          // A col 0 or 8
    const int rb = tid >> 4;               // B row 0..15
    const int cb = (tid & 15) * 8;         // B col 0..120

    const float* Aptr = A + ra * lda + ca;
    const float* Bptr = B + rb * ldb + cb;

    float4 a0 = *(const float4*)Aptr;
    float4 a1 = *(const float4*)(Aptr + 4);
    float4 b0 = *(const float4*)Bptr;
    float4 b1 = *(const float4*)(Bptr + 4);

    uint32_t* Asb = As;
    uint32_t* Bsb = Bs;
    Asb[ra * ASTR + ca + 0] = f2tf(a0.x); Asb[ra * ASTR + ca + 1] = f2tf(a0.y);
    Asb[ra * ASTR + ca + 2] = f2tf(a0.z); Asb[ra * ASTR + ca + 3] = f2tf(a0.w);
    Asb[ra * ASTR + ca + 4] = f2tf(a1.x); Asb[ra * ASTR + ca + 5] = f2tf(a1.y);
    Asb[ra * ASTR + ca + 6] = f2tf(a1.z); Asb[ra * ASTR + ca + 7] = f2tf(a1.w);
    Bsb[rb * BSTR + cb + 0] = f2tf(b0.x); Bsb[rb * BSTR + cb + 1] = f2tf(b0.y);
    Bsb[rb * BSTR + cb + 2] = f2tf(b0.z); Bsb[rb * BSTR + cb + 3] = f2tf(b0.w);
    Bsb[rb * BSTR + cb + 4] = f2tf(b1.x); Bsb[rb * BSTR + cb + 5] = f2tf(b1.y);
    Bsb[rb * BSTR + cb + 6] = f2tf(b1.z); Bsb[rb * BSTR + cb + 7] = f2tf(b1.w);
    __syncthreads();

    float acc[2][8][4] = {};
    const int ntiles = Kdim / 16;

    for (int kt = 0; kt < ntiles; kt++) {
        const int cur = kt & 1;
        if (kt + 1 < ntiles) {
            a0 = *(const float4*)(Aptr + (kt + 1) * 16);
            a1 = *(const float4*)(Aptr + (kt + 1) * 16 + 4);
            b0 = *(const float4*)(Bptr + (kt + 1) * 16 * ldb);
            b1 = *(const float4*)(Bptr + (kt + 1) * 16 * ldb + 4);
        }
        const uint32_t* Ac = As + cur * (128 * ASTR);
        const uint32_t* Bc = Bs + cur * (16 * BSTR);

        #pragma unroll
        for (int h = 0; h < 2; h++) {
            const int k0 = h * 8;
            uint32_t afr[2][4], bfr[8][2];
            #pragma unroll
            for (int tm = 0; tm < 2; tm++) {
                const int mb = mw + tm * 16;
                afr[tm][0] = Ac[(mb + g)     * ASTR + k0 + t];
                afr[tm][1] = Ac[(mb + g + 8) * ASTR + k0 + t];
                afr[tm][2] = Ac[(mb + g)     * ASTR + k0 + t + 4];
                afr[tm][3] = Ac[(mb + g + 8) * ASTR + k0 + t + 4];
            }
            #pragma unroll
            for (int tn = 0; tn < 8; tn++) {
                const int nb = nw + tn * 8 + g;
                bfr[tn][0] = Bc[(k0 + t)     * BSTR + nb];
                bfr[tn][1] = Bc[(k0 + t + 4) * BSTR + nb];
            }
            #pragma unroll
            for (int tm = 0; tm < 2; tm++)
                #pragma unroll
                for (int tn = 0; tn < 8; tn++)
                    mma8(acc[tm][tn], afr[tm], bfr[tn]);
        }

        if (kt + 1 < ntiles) {
            const int nxt = cur ^ 1;
            uint32_t* An = As + nxt * (128 * ASTR);
            uint32_t* Bn = Bs + nxt * (16 * BSTR);
            An[ra * ASTR + ca + 0] = f2tf(a0.x); An[ra * ASTR + ca + 1] = f2tf(a0.y);
            An[ra * ASTR + ca + 2] = f2tf(a0.z); An[ra * ASTR + ca + 3] = f2tf(a0.w);
            An[ra * ASTR + ca + 4] = f2tf(a1.x); An[ra * ASTR + ca + 5] = f2tf(a1.y);
            An[ra * ASTR + ca + 6] = f2tf(a1.z); An[ra * ASTR + ca + 7] = f2tf(a1.w);
            Bn[rb * BSTR + cb + 0] = f2tf(b0.x); Bn[rb * BSTR + cb + 1] = f2tf(b0.y);
            Bn[rb * BSTR + cb + 2] = f2tf(b0.z); Bn[rb * BSTR + cb + 3] = f2tf(b0.w);
            Bn[rb * BSTR + cb + 4] = f2tf(b1.x); Bn[rb * BSTR + cb + 5] = f2tf(b1.y);
            Bn[rb * BSTR + cb + 6] = f2tf(b1.z); Bn[rb * BSTR + cb + 7] = f2tf(b1.w);
        }
        __syncthreads();
    }

    #pragma unroll
    for (int tm = 0; tm < 2; tm++) {
        #pragma unroll
        for (int tn = 0; tn < 8; tn++) {
            const int r0 = mw + tm * 16 + g;
            const int cc = nw + tn * 8 + 2 * t;
            *(float2*)&C[r0 * ldc + cc]       = make_float2(acc[tm][tn][0], acc[tm][tn][1]);
            *(float2*)&C[(r0 + 8) * ldc + cc] = make_float2(acc[tm][tn][2], acc[tm][tn][3]);
        }
    }
}

#define GEMM_SMEM (2 * 128 * ASTR + 2 * 16 * BSTR)

// qg projection, both streams fused: grid (16, 2, 16)
__global__ __launch_bounds__(256, 2) void proj_qg_kernel(
    const float* __restrict__ x0, const float* __restrict__ x1,
    const float* __restrict__ w0, const float* __restrict__ w1,
    float* __restrict__ qg)
{
    __shared__ uint32_t sm[GEMM_SMEM];
    const int tile = blockIdx.x;
    const int bn = blockIdx.y * 128;
    const int n = blockIdx.z;
    const float* A = (tile < 4) ? (x0 + (long)tile * 128 * WIDTH)
                                : (x1 + (long)(tile - 4) * 128 * WIDTH);
    const float* B = ((tile < 4) ? w0 : w1) + (long)n * WIDTH * 256 + bn;
    float* C = qg + (long)tile * 128 * (NH * 256) + n * 256 + bn;
    mma_gemm_core(A, WIDTH, B, 256, C, NH * 256, WIDTH, sm, sm + 2 * 128 * ASTR);
}

// K+V projections fused: grid (16, 1, 8). z<4: K->kraw, z>=4: V->vcache
__global__ __launch_bounds__(256, 2) void proj_kv_kernel(
    const float* __restrict__ x0, const float* __restrict__ x1,
    const float* __restrict__ kw0, const float* __restrict__ kw1,
    const float* __restrict__ vw0, const float* __restrict__ vw1,
    float* __restrict__ kraw, float* __restrict__ vcache)
{
    __shared__ uint32_t sm[GEMM_SMEM];
    const int tile = blockIdx.x;
    const int z = blockIdx.z;
    const bool isV = (z >= 4);
    const int kk = z & 3;
    const float* A = (tile < 4) ? (x0 + (long)tile * 128 * WIDTH)
                                : (x1 + (long)(tile - 4) * 128 * WIDTH);
    const float* W = isV ? ((tile < 4) ? vw0 : vw1) : ((tile < 4) ? kw0 : kw1);
    const float* B = W + (long)kk * WIDTH * HD;
    float* Cb = isV ? vcache : kraw;
    float* C = Cb + (long)tile * 128 * (KH * HD) + kk * HD;
    mma_gemm_core(A, WIDTH, B, HD, C, KH * HD, WIDTH, sm, sm + 2 * 128 * ASTR);
}

// output projection fused: grid (16, 16)
__global__ __launch_bounds__(256, 2) void proj_out_kernel(
    const float* __restrict__ enc,
    const float* __restrict__ ow0, const float* __restrict__ ow1,
    float* __restrict__ out)
{
    __shared__ uint32_t sm[GEMM_SMEM];
    const int tile = blockIdx.x;
    const int bn = blockIdx.y * 128;
    const float* A = enc + (long)tile * 128 * (NH * HD);
    const float* B = ((tile < 4) ? ow0 : ow1) + bn;
    float* C = out + (long)tile * 128 * WIDTH + bn;
    mma_gemm_core(A, NH * HD, B, WIDTH, C, WIDTH, NH * HD, sm, sm + 2 * 128 * ASTR);
}

// ---------------------------------------------------------------------------
// RMSNorm + RoPE for Q
// ---------------------------------------------------------------------------
__global__ __launch_bounds__(128) void qnorm_rope(
    const float* __restrict__ qg, float* __restrict__ qout,
    const int* __restrict__ positions,
    const float* __restrict__ qn0, const float* __restrict__ qn1)
{
    int row  = blockIdx.x * 4 + (threadIdx.x >> 5);
    int lane = threadIdx.x & 31;
    int t = row >> 4;
    int n = row & 15;
    const float* src = qg + t * (NH * 256) + n * 256;

    float v0 = src[lane];
    float v1 = src[lane + 32];
    float v2 = src[lane + 64];
    float v3 = src[lane + 96];
    float ss = v0 * v0 + v1 * v1 + v2 * v2 + v3 * v3;
    #pragma unroll
    for (int o = 16; o; o >>= 1) ss += __shfl_xor_sync(0xffffffffu, ss, o);
    float inv = rsqrtf(ss * (1.0f / 128.0f) + 1e-6f);

    const float* qn = (t < T0) ? qn0 : qn1;
    v0 = v0 * inv * (1.0f + qn[lane]);
    v1 = v1 * inv * (1.0f + qn[lane + 32]);
    v2 = v2 * inv * (1.0f + qn[lane + 64]);
    v3 = v3 * inv * (1.0f + qn[lane + 96]);

    float p = (float)positions[t];
    float freq = powf(1000000.0f, -(float)lane / 32.0f);
    float s, c;
    sincosf(p * freq, &s, &c);

    const float SCL = 0.08838834764831845f;
    float* dst = qout + t * (NH * HD) + n * HD;
    dst[lane]      = (v0 * c - v1 * s) * SCL;
    dst[lane + 32] = (v1 * c + v0 * s) * SCL;
    dst[lane + 64] = v2 * SCL;
    dst[lane + 96] = v3 * SCL;
}

__global__ __launch_bounds__(128) void knorm_rope(
    const float* __restrict__ kraw, float* __restrict__ kcache,
    const int* __restrict__ positions,
    const float* __restrict__ kn0, const float* __restrict__ kn1)
{
    int row  = blockIdx.x * 4 + (threadIdx.x >> 5);
    int lane = threadIdx.x & 31;
    int t  = row >> 2;
    int kk = row & 3;
    const float* src = kraw + t * (KH * HD) + kk * HD;

    float v0 = src[lane];
    float v1 = src[lane + 32];
    float v2 = src[lane + 64];
    float v3 = src[lane + 96];
    float ss = v0 * v0 + v1 * v1 + v2 * v2 + v3 * v3;
    #pragma unroll
    for (int o = 16; o; o >>= 1) ss += __shfl_xor_sync(0xffffffffu, ss, o);
    float inv = rsqrtf(ss * (1.0f / 128.0f) + 1e-6f);

    const float* kn = (t < T0) ? kn0 : kn1;
    v0 = v0 * inv * (1.0f + kn[lane]);
    v1 = v1 * inv * (1.0f + kn[lane + 32]);
    v2 = v2 * inv * (1.0f + kn[lane + 64]);
    v3 = v3 * inv * (1.0f + kn[lane + 96]);

    float p = (float)positions[t];
    float freq = powf(1000000.0f, -(float)lane / 32.0f);
    float s, c;
    sincosf(p * freq, &s, &c);

    float* dst = kcache + t * (KH * HD) + kk * HD;
    dst[lane]      = v0 * c - v1 * s;
    dst[lane + 32] = v1 * c + v0 * s;
    dst[lane + 64] = v2;
    dst[lane + 96] = v3;
}

// ---------------------------------------------------------------------------
// Flash attention with tf32 MMA. Block = (64-query tile, head), 256 threads.
// Qs [64][132] tf32, Ks/Vs [64][136] tf32 (row-major, no transpose),
// Ss [64][72] fp32.
// ---------------------------------------------------------------------------
#define QSTR 132
#define KSTR 136
#define SSTR 72
#define ATT_QS   0
#define ATT_KS   (64 * QSTR)
#define ATT_SS   (ATT_KS + 64 * KSTR)
#define ATT_SMEM ((ATT_SS + 64 * SSTR))

__global__ __launch_bounds__(256, 2) void attn_kernel(
    const float* __restrict__ q, const float* __restrict__ kc,
    const float* __restrict__ vc, float* __restrict__ enc)
{
    extern __shared__ uint32_t sm[];
    uint32_t* Qs = sm + ATT_QS;
    uint32_t* Ks = sm + ATT_KS;   // union with Vs
    float*    Ss = (float*)(sm + ATT_SS);
    __shared__ float m_s[64], l_s[64], a_s[64];

    const int tid = threadIdx.x;
    const int lane = tid & 31;
    const int g = lane >> 2;
    const int t = lane & 3;
    const int wid = tid >> 5;
    const int wm = (wid >> 1) * 16;  // warp row base (both phases)
    const int wn = wid & 1;          // warp col half
    const int qt = blockIdx.x;
    const int n  = blockIdx.y;
    const int kvh = n >> 2;
    const int qbase = qt * 64;

    for (int idx = tid; idx < 64 * 128; idx += 256) {
        int r = idx >> 7, c = idx & 127;
        Qs[r * QSTR + c] = f2tf(q[(qbase + r) * (NH * HD) + n * HD + c]);
    }
    if (tid < 64) { m_s[tid] = -3.0e38f; l_s[tid] = 0.0f; }

    float accO[8][4] = {};   // PV accum: rows wm+g/(+8), cols wn*64 + tn*8 + 2t

    for (int j = 0; j <= qt; j++) {
        __syncthreads();
        const int sb = j * 64;
        for (int idx = tid; idx < 64 * 128; idx += 256) {
            int s = idx >> 7, c = idx & 127;
            Ks[s * KSTR + c] = f2tf(kc[(sb + s) * (KH * HD) + kvh * HD + c]);
        }
        __syncthreads();

        // ---- S = Q K^T (64x64). Warp tile 16 x 32 (wn*32). ----
        float sacc[4][4] = {};
        #pragma unroll
        for (int ks = 0; ks < 16; ks++) {
            const int k0 = ks * 8;
            uint32_t afr[4], bfr[4][2];
            afr[0] = Qs[(wm + g)     * QSTR + k0 + t];
            afr[1] = Qs[(wm + g + 8) * QSTR + k0 + t];
            afr[2] = Qs[(wm + g)     * QSTR + k0 + t + 4];
            afr[3] = Qs[(wm + g + 8) * QSTR + k0 + t + 4];
            #pragma unroll
            for (int tn = 0; tn < 4; tn++) {
                const int key = wn * 32 + tn * 8 + g;
                bfr[tn][0] = Ks[key * KSTR + k0 + t];
                bfr[tn][1] = Ks[key * KSTR + k0 + t + 4];
            }
            #pragma unroll
            for (int tn = 0; tn < 4; tn++) mma8(sacc[tn], afr, bfr[tn]);
        }
        // write S to smem with causal mask
        const bool diag = (j == qt);
        #pragma unroll
        for (int tn = 0; tn < 4; tn++) {
            const int cc = wn * 32 + tn * 8 + 2 * t;
            const int r0 = wm + g, r1 = wm + g + 8;
            float v0 = sacc[tn][0], v1 = sacc[tn][1];
            float v2 = sacc[tn][2], v3 = sacc[tn][3];
            if (diag) {
                if (cc     > r0) v0 = NEGV;
                if (cc + 1 > r0) v1 = NEGV;
                if (cc     > r1) v2 = NEGV;
                if (cc + 1 > r1) v3 = NEGV;
            }
            Ss[r0 * SSTR + cc] = v0; Ss[r0 * SSTR + cc + 1] = v1;
            Ss[r1 * SSTR + cc] = v2; Ss[r1 * SSTR + cc + 1] = v3;
        }
        __syncthreads();

        // ---- load V (overwrites Ks) — independent of softmax on Ss ----
        for (int idx = tid; idx < 64 * 128; idx += 256) {
            int s = idx >> 7, c = idx & 127;
            Ks[s * KSTR + c] = f2tf(vc[(sb + s) * (KH * HD) + kvh * HD + c]);
        }

        // ---- online softmax: 4 threads per row; store P tf32-rounded ----
        {
            int r = tid >> 2;
            int qq = tid & 3;
            float* row = Ss + r * SSTR + qq * 16;
            float mold = m_s[r];
            float rmax = -3.0e38f;
            #pragma unroll
            for (int c = 0; c < 16; c++) rmax = fmaxf(rmax, row[c]);
            rmax = fmaxf(rmax, __shfl_xor_sync(0xffffffffu, rmax, 1));
            rmax = fmaxf(rmax, __shfl_xor_sync(0xffffffffu, rmax, 2));
            float mn = fmaxf(mold, rmax);
            float sum = 0.0f;
            #pragma unroll
            for (int c = 0; c < 16; c++) {
                float pv = __expf(row[c] - mn);
                sum += pv;
                row[c] = __uint_as_float(f2tf(pv));
            }
            sum += __shfl_xor_sync(0xffffffffu, sum, 1);
            sum += __shfl_xor_sync(0xffffffffu, sum, 2);
            if (qq == 0) {
                float al = __expf(mold - mn);
                l_s[r] = l_s[r] * al + sum;
                m_s[r] = mn;
                a_s[r] = al;
            }
        }
        __syncthreads();

        // ---- rescale + O += P V. Warp tile 16 x 64 (wn*64). ----
        const float al0 = a_s[wm + g];
        const float al1 = a_s[wm + g + 8];
        #pragma unroll
        for (int tn = 0; tn < 8; tn++) {
            accO[tn][0] *= al0; accO[tn][1] *= al0;
            accO[tn][2] *= al1; accO[tn][3] *= al1;
        }
        const uint32_t* Ps = (const uint32_t*)Ss;
        #pragma unroll
        for (int ks = 0; ks < 8; ks++) {
            const int k0 = ks * 8;
            uint32_t afr[4], bfr[8][2];
            afr[0] = Ps[(wm + g)     * SSTR + k0 + t];
            afr[1] = Ps[(wm + g + 8) * SSTR + k0 + t];
            afr[2] = Ps[(wm + g)     * SSTR + k0 + t + 4];
            afr[3] = Ps[(wm + g + 8) * SSTR + k0 + t + 4];
            #pragma unroll
            for (int tn = 0; tn < 8; tn++) {
                const int hb = wn * 64 + tn * 8 + g;
                bfr[tn][0] = Ks[(k0 + t)     * KSTR + hb];
                bfr[tn][1] = Ks[(k0 + t + 4) * KSTR + hb];
            }
            #pragma unroll
            for (int tn = 0; tn < 8; tn++) mma8(accO[tn], afr, bfr[tn]);
        }
    }

    const float inv0 = 1.0f / l_s[wm + g];
    const float inv1 = 1.0f / l_s[wm + g + 8];
    #pragma unroll
    for (int tn = 0; tn < 8; tn++) {
        const int cc = wn * 64 + tn * 8 + 2 * t;
        float* d0 = enc + (qbase + wm + g) * (NH * HD) + n * HD + cc;
        float* d1 = enc + (qbase + wm + g + 8) * (NH * HD) + n * HD + cc;
        *(float2*)d0 = make_float2(accO[tn][0] * inv0, accO[tn][1] * inv0);
        *(float2*)d1 = make_float2(accO[tn][2] * inv1, accO[tn][3] * inv1);
    }
}

// enc *= sigmoid(gate)
__global__ __launch_bounds__(256) void gate_kernel(
    const float* __restrict__ qg, float* __restrict__ enc)
{
    int idx = blockIdx.x * 256 + threadIdx.x;
    int t = idx >> 11;
    int rem = idx & 2047;
    int n = rem >> 7;
    int h = rem & 127;
    float g = qg[t * (NH * 256) + n * 256 + 128 + h];
    enc[idx] *= 1.0f / (1.0f + __expf(-g));
}

// ---------------------------------------------------------------------------
extern "C" void kernel_launch(void* const* d_in, const int* in_sizes, int n_in,
                              void* d_out, int out_size)
{
    const float* x0    = (const float*)d_in[0];
    const float* x1    = (const float*)d_in[1];
    const int*   pos   = (const int*)d_in[2];
    const float* qg_w0 = (const float*)d_in[4];
    const float* k_w0  = (const float*)d_in[5];
    const float* v_w0  = (const float*)d_in[6];
    const float* qn0   = (const float*)d_in[7];
    const float* kn0   = (const float*)d_in[8];
    const float* o_w0  = (const float*)d_in[9];
    const float* qg_w1 = (const float*)d_in[10];
    const float* k_w1  = (const float*)d_in[11];
    const float* v_w1  = (const float*)d_in[12];
    const float* qn1   = (const float*)d_in[13];
    const float* kn1   = (const float*)d_in[14];
    const float* o_w1  = (const float*)d_in[15];

    float* out = (float*)d_out;

    float *qg, *kraw, *q, *enc;
    cudaGetSymbolAddress((void**)&qg,   g_qg);
    cudaGetSymbolAddress((void**)&kraw, g_kraw);
    cudaGetSymbolAddress((void**)&q,    g_q);
    cudaGetSymbolAddress((void**)&enc,  g_enc);

    // projections (tf32 MMA)
    proj_qg_kernel<<<dim3(16, 2, 16), 256>>>(x0, x1, qg_w0, qg_w1, qg);
    proj_kv_kernel<<<dim3(16, 1, 8), 256>>>(x0, x1, k_w0, k_w1, v_w0, v_w1,
                                            kraw, out + VC_BASE);

    // norms + rope
    qnorm_rope<<<TT*NH/4, 128>>>(qg, q, pos, qn0, qn1);
    knorm_rope<<<TT*KH/4, 128>>>(kraw, out + KC_BASE, pos, kn0, kn1);

    // attention (tf32 MMA flash)
    cudaFuncSetAttribute(attn_kernel, cudaFuncAttributeMaxDynamicSharedMemorySize,
                         ATT_SMEM * sizeof(uint32_t));
    attn_kernel<<<dim3(TT/64, NH), 256, ATT_SMEM * sizeof(uint32_t)>>>(
        q, out + KC_BASE, out + VC_BASE, enc);

    // gate + output projection
    gate_kernel<<<TT*NH*HD/256, 256>>>(qg, enc);
    proj_out_kernel<<<dim3(16, 16), 256>>>(enc, o_w0, o_w1, out);
}

// round 5
// speedup vs baseline: 3.7447x; 1.2302x over previous
#include <cuda_runtime.h>
#include <cuda_bf16.h>
#include <math.h>
#include <stdint.h>

// Problem constants
#define T0 512
#define TT 2048
#define WIDTH 2048
#define NH 16
#define KH 4
#define HD 128
#define KC_BASE (TT*WIDTH)
#define VC_BASE (KC_BASE + TT*KH*HD)
#define NEGV -2.3819763e38f

// Scratch
__device__ float g_qg[TT * NH * 256];
__device__ float g_kraw[TT * KH * HD];
__device__ float g_q[TT * NH * HD];
__device__ float g_enc[TT * NH * HD];

// ---------------------------------------------------------------------------
// helpers
// ---------------------------------------------------------------------------
__device__ __forceinline__ uint32_t f2tf(float f) {
    uint32_t r;
    asm("cvt.rna.tf32.f32 %0, %1;" : "=r"(r) : "f"(f));
    return r;
}

__device__ __forceinline__ uint32_t smem_u32(const void* p) {
    uint32_t a;
    asm("{ .reg .u64 t; cvta.to.shared.u64 t, %1; cvt.u32.u64 %0, t; }"
        : "=r"(a) : "l"(p));
    return a;
}

__device__ __forceinline__ void cpasync16(uint32_t s, const float* g) {
    asm volatile("cp.async.ca.shared.global [%0], [%1], 16;" :: "r"(s), "l"(g));
}

// m16n8k8 tf32 MMA, fp32 accumulate.
__device__ __forceinline__ void mma8(float* c, const uint32_t* a, const uint32_t* b) {
    asm volatile(
        "mma.sync.aligned.m16n8k8.row.col.f32.tf32.tf32.f32 "
        "{%0,%1,%2,%3},{%4,%5,%6,%7},{%8,%9},{%0,%1,%2,%3};"
        : "+f"(c[0]), "+f"(c[1]), "+f"(c[2]), "+f"(c[3])
        : "r"(a[0]), "r"(a[1]), "r"(a[2]), "r"(a[3]), "r"(b[0]), "r"(b[1]));
}

// ---------------------------------------------------------------------------
// cp.async pipelined tf32 GEMM core.
// 128x128 block tile, BK=16, 256 threads (8 warps, 32x64 warp tile), 3 stages.
// fp32 staged in smem; tf32 convert at fragment build.  Kdim % 16 == 0, >= 32.
// ---------------------------------------------------------------------------
#define ASTRF 20
#define BSTRF 136
#define A_STAGE (128 * ASTRF)              // floats
#define B_STAGE (16 * BSTRF)
#define STAGE_F (A_STAGE + B_STAGE)
#define NSTAGE 3
#define GEMM_SMEM_BYTES (NSTAGE * STAGE_F * 4)

__device__ __forceinline__ void issue_stage(
    uint32_t sbase, int stage, const float* A, int lda,
    const float* B, int ldb, int k0, int tid)
{
    const uint32_t aS = sbase + stage * (STAGE_F * 4);
    const uint32_t bS = aS + A_STAGE * 4;
    const int ar = tid >> 2, ak = (tid & 3) * 4;
    const int br = tid >> 5, bc = (tid & 31) * 4;
    cpasync16(aS + (ar * ASTRF + ak) * 4,          A + (long)ar * lda + k0 + ak);
    cpasync16(aS + ((64 + ar) * ASTRF + ak) * 4,   A + (long)(64 + ar) * lda + k0 + ak);
    cpasync16(bS + (br * BSTRF + bc) * 4,          B + (long)(k0 + br) * ldb + bc);
    cpasync16(bS + ((8 + br) * BSTRF + bc) * 4,    B + (long)(k0 + 8 + br) * ldb + bc);
    asm volatile("cp.async.commit_group;" ::: "memory");
}

__device__ void gemm_async_core(
    const float* __restrict__ A, int lda,
    const float* __restrict__ B, int ldb,
    float* __restrict__ C, int ldc, int Kdim)
{
    extern __shared__ float smf[];
    const uint32_t sbase = smem_u32(smf);

    const int tid = threadIdx.x;
    const int lane = tid & 31;
    const int g = lane >> 2;
    const int t = lane & 3;
    const int wid = tid >> 5;
    const int mw = (wid >> 1) * 32;
    const int nw = (wid & 1) * 64;

    const int nt = Kdim / 16;

    issue_stage(sbase, 0, A, lda, B, ldb, 0, tid);
    issue_stage(sbase, 1, A, lda, B, ldb, 16, tid);

    float acc[2][8][4] = {};

    for (int kt = 0; kt < nt; kt++) {
        if (kt + 2 < nt) {
            issue_stage(sbase, (kt + 2) % 3, A, lda, B, ldb, (kt + 2) * 16, tid);
            asm volatile("cp.async.wait_group %0;" :: "n"(2) : "memory");
        } else if (kt + 1 < nt) {
            asm volatile("cp.async.wait_group %0;" :: "n"(1) : "memory");
        } else {
            asm volatile("cp.async.wait_group %0;" :: "n"(0) : "memory");
        }
        __syncthreads();

        const float* AsF = smf + (kt % 3) * STAGE_F;
        const float* BsF = AsF + A_STAGE;

        #pragma unroll
        for (int h = 0; h < 2; h++) {
            const int k0 = h * 8;
            uint32_t afr[2][4], bfr[8][2];
            #pragma unroll
            for (int tm = 0; tm < 2; tm++) {
                const int mb = mw + tm * 16;
                afr[tm][0] = f2tf(AsF[(mb + g)     * ASTRF + k0 + t]);
                afr[tm][1] = f2tf(AsF[(mb + g + 8) * ASTRF + k0 + t]);
                afr[tm][2] = f2tf(AsF[(mb + g)     * ASTRF + k0 + t + 4]);
                afr[tm][3] = f2tf(AsF[(mb + g + 8) * ASTRF + k0 + t + 4]);
            }
            #pragma unroll
            for (int tn = 0; tn < 8; tn++) {
                const int nb = nw + tn * 8 + g;
                bfr[tn][0] = f2tf(BsF[(k0 + t)     * BSTRF + nb]);
                bfr[tn][1] = f2tf(BsF[(k0 + t + 4) * BSTRF + nb]);
            }
            #pragma unroll
            for (int tm = 0; tm < 2; tm++)
                #pragma unroll
                for (int tn = 0; tn < 8; tn++)
                    mma8(acc[tm][tn], afr[tm], bfr[tn]);
        }
        __syncthreads();
    }

    #pragma unroll
    for (int tm = 0; tm < 2; tm++) {
        #pragma unroll
        for (int tn = 0; tn < 8; tn++) {
            const int r0 = mw + tm * 16 + g;
            const int cc = nw + tn * 8 + 2 * t;
            *(float2*)&C[r0 * ldc + cc]       = make_float2(acc[tm][tn][0], acc[tm][tn][1]);
            *(float2*)&C[(r0 + 8) * ldc + cc] = make_float2(acc[tm][tn][2], acc[tm][tn][3]);
        }
    }
}

// ---------------------------------------------------------------------------
// Fused projections: qg (y 0..31), K (y 32..35), V (y 36..39). grid (16, 40).
// ---------------------------------------------------------------------------
__global__ __launch_bounds__(256, 2) void proj_fused_kernel(
    const float* __restrict__ x0, const float* __restrict__ x1,
    const float* __restrict__ qgw0, const float* __restrict__ qgw1,
    const float* __restrict__ kw0, const float* __restrict__ kw1,
    const float* __restrict__ vw0, const float* __restrict__ vw1,
    float* __restrict__ qg, float* __restrict__ kraw, float* __restrict__ vcache)
{
    const int tile = blockIdx.x;
    const int y = blockIdx.y;
    const float* A = (tile < 4) ? (x0 + (long)tile * 128 * WIDTH)
                                : (x1 + (long)(tile - 4) * 128 * WIDTH);
    const float* B;
    float* C;
    int ldb, ldc;
    if (y < 32) {
        const int n = y >> 1, bn = (y & 1) * 128;
        B = ((tile < 4) ? qgw0 : qgw1) + (long)n * WIDTH * 256 + bn;
        ldb = 256;
        C = qg + (long)tile * 128 * (NH * 256) + n * 256 + bn;
        ldc = NH * 256;
    } else if (y < 36) {
        const int kk = y - 32;
        B = ((tile < 4) ? kw0 : kw1) + (long)kk * WIDTH * HD;
        ldb = HD;
        C = kraw + (long)tile * 128 * (KH * HD) + kk * HD;
        ldc = KH * HD;
    } else {
        const int kk = y - 36;
        B = ((tile < 4) ? vw0 : vw1) + (long)kk * WIDTH * HD;
        ldb = HD;
        C = vcache + (long)tile * 128 * (KH * HD) + kk * HD;
        ldc = KH * HD;
    }
    gemm_async_core(A, WIDTH, B, ldb, C, ldc, WIDTH);
}

// output projection: grid (16, 16)
__global__ __launch_bounds__(256, 2) void proj_out_kernel(
    const float* __restrict__ enc,
    const float* __restrict__ ow0, const float* __restrict__ ow1,
    float* __restrict__ out)
{
    const int tile = blockIdx.x;
    const int bn = blockIdx.y * 128;
    const float* A = enc + (long)tile * 128 * (NH * HD);
    const float* B = ((tile < 4) ? ow0 : ow1) + bn;
    float* C = out + (long)tile * 128 * WIDTH + bn;
    gemm_async_core(A, NH * HD, B, WIDTH, C, WIDTH, NH * HD);
}

// ---------------------------------------------------------------------------
// RMSNorm + RoPE
// ---------------------------------------------------------------------------
__global__ __launch_bounds__(128) void qnorm_rope(
    const float* __restrict__ qg, float* __restrict__ qout,
    const int* __restrict__ positions,
    const float* __restrict__ qn0, const float* __restrict__ qn1)
{
    int row  = blockIdx.x * 4 + (threadIdx.x >> 5);
    int lane = threadIdx.x & 31;
    int t = row >> 4;
    int n = row & 15;
    const float* src = qg + t * (NH * 256) + n * 256;

    float v0 = src[lane];
    float v1 = src[lane + 32];
    float v2 = src[lane + 64];
    float v3 = src[lane + 96];
    float ss = v0 * v0 + v1 * v1 + v2 * v2 + v3 * v3;
    #pragma unroll
    for (int o = 16; o; o >>= 1) ss += __shfl_xor_sync(0xffffffffu, ss, o);
    float inv = rsqrtf(ss * (1.0f / 128.0f) + 1e-6f);

    const float* qn = (t < T0) ? qn0 : qn1;
    v0 = v0 * inv * (1.0f + qn[lane]);
    v1 = v1 * inv * (1.0f + qn[lane + 32]);
    v2 = v2 * inv * (1.0f + qn[lane + 64]);
    v3 = v3 * inv * (1.0f + qn[lane + 96]);

    float p = (float)positions[t];
    float freq = powf(1000000.0f, -(float)lane / 32.0f);
    float s, c;
    sincosf(p * freq, &s, &c);

    const float SCL = 0.08838834764831845f;
    float* dst = qout + t * (NH * HD) + n * HD;
    dst[lane]      = (v0 * c - v1 * s) * SCL;
    dst[lane + 32] = (v1 * c + v0 * s) * SCL;
    dst[lane + 64] = v2 * SCL;
    dst[lane + 96] = v3 * SCL;
}

__global__ __launch_bounds__(128) void knorm_rope(
    const float* __restrict__ kraw, float* __restrict__ kcache,
    const int* __restrict__ positions,
    const float* __restrict__ kn0, const float* __restrict__ kn1)
{
    int row  = blockIdx.x * 4 + (threadIdx.x >> 5);
    int lane = threadIdx.x & 31;
    int t  = row >> 2;
    int kk = row & 3;
    const float* src = kraw + t * (KH * HD) + kk * HD;

    float v0 = src[lane];
    float v1 = src[lane + 32];
    float v2 = src[lane + 64];
    float v3 = src[lane + 96];
    float ss = v0 * v0 + v1 * v1 + v2 * v2 + v3 * v3;
    #pragma unroll
    for (int o = 16; o; o >>= 1) ss += __shfl_xor_sync(0xffffffffu, ss, o);
    float inv = rsqrtf(ss * (1.0f / 128.0f) + 1e-6f);

    const float* kn = (t < T0) ? kn0 : kn1;
    v0 = v0 * inv * (1.0f + kn[lane]);
    v1 = v1 * inv * (1.0f + kn[lane + 32]);
    v2 = v2 * inv * (1.0f + kn[lane + 64]);
    v3 = v3 * inv * (1.0f + kn[lane + 96]);

    float p = (float)positions[t];
    float freq = powf(1000000.0f, -(float)lane / 32.0f);
    float s, c;
    sincosf(p * freq, &s, &c);

    float* dst = kcache + t * (KH * HD) + kk * HD;
    dst[lane]      = v0 * c - v1 * s;
    dst[lane + 32] = v1 * c + v0 * s;
    dst[lane + 64] = v2;
    dst[lane + 96] = v3;
}

// ---------------------------------------------------------------------------
// Flash attention with tf32 mma.sync + fused sigmoid gate epilogue.
// Heavy (late) q-tiles scheduled first.
// ---------------------------------------------------------------------------
#define QSTR 132
#define KSTR 136
#define SSTR 72
#define ATT_QS   0
#define ATT_KS   (64 * QSTR)
#define ATT_SS   (ATT_KS + 64 * KSTR)
#define ATT_SMEM ((ATT_SS + 64 * SSTR))

__global__ __launch_bounds__(256, 2) void attn_kernel(
    const float* __restrict__ q, const float* __restrict__ kc,
    const float* __restrict__ vc, const float* __restrict__ qg,
    float* __restrict__ enc)
{
    extern __shared__ uint32_t sm[];
    uint32_t* Qs = sm + ATT_QS;
    uint32_t* Ks = sm + ATT_KS;
    float*    Ss = (float*)(sm + ATT_SS);
    __shared__ float m_s[64], l_s[64], a_s[64];

    const int tid = threadIdx.x;
    const int lane = tid & 31;
    const int g = lane >> 2;
    const int t = lane & 3;
    const int wid = tid >> 5;
    const int wm = (wid >> 1) * 16;
    const int wn = wid & 1;
    const int qt = gridDim.x - 1 - blockIdx.x;   // heavy tiles first
    const int n  = blockIdx.y;
    const int kvh = n >> 2;
    const int qbase = qt * 64;

    for (int idx = tid; idx < 64 * 128; idx += 256) {
        int r = idx >> 7, c = idx & 127;
        Qs[r * QSTR + c] = f2tf(q[(qbase + r) * (NH * HD) + n * HD + c]);
    }
    if (tid < 64) { m_s[tid] = -3.0e38f; l_s[tid] = 0.0f; }

    float accO[8][4] = {};

    for (int j = 0; j <= qt; j++) {
        __syncthreads();
        const int sb = j * 64;
        for (int idx = tid; idx < 64 * 128; idx += 256) {
            int s = idx >> 7, c = idx & 127;
            Ks[s * KSTR + c] = f2tf(kc[(sb + s) * (KH * HD) + kvh * HD + c]);
        }
        __syncthreads();

        float sacc[4][4] = {};
        #pragma unroll
        for (int ks = 0; ks < 16; ks++) {
            const int k0 = ks * 8;
            uint32_t afr[4], bfr[4][2];
            afr[0] = Qs[(wm + g)     * QSTR + k0 + t];
            afr[1] = Qs[(wm + g + 8) * QSTR + k0 + t];
            afr[2] = Qs[(wm + g)     * QSTR + k0 + t + 4];
            afr[3] = Qs[(wm + g + 8) * QSTR + k0 + t + 4];
            #pragma unroll
            for (int tn = 0; tn < 4; tn++) {
                const int key = wn * 32 + tn * 8 + g;
                bfr[tn][0] = Ks[key * KSTR + k0 + t];
                bfr[tn][1] = Ks[key * KSTR + k0 + t + 4];
            }
            #pragma unroll
            for (int tn = 0; tn < 4; tn++) mma8(sacc[tn], afr, bfr[tn]);
        }
        const bool diag = (j == qt);
        #pragma unroll
        for (int tn = 0; tn < 4; tn++) {
            const int cc = wn * 32 + tn * 8 + 2 * t;
            const int r0 = wm + g, r1 = wm + g + 8;
            float v0 = sacc[tn][0], v1 = sacc[tn][1];
            float v2 = sacc[tn][2], v3 = sacc[tn][3];
            if (diag) {
                if (cc     > r0) v0 = NEGV;
                if (cc + 1 > r0) v1 = NEGV;
                if (cc     > r1) v2 = NEGV;
                if (cc + 1 > r1) v3 = NEGV;
            }
            Ss[r0 * SSTR + cc] = v0; Ss[r0 * SSTR + cc + 1] = v1;
            Ss[r1 * SSTR + cc] = v2; Ss[r1 * SSTR + cc + 1] = v3;
        }
        __syncthreads();

        for (int idx = tid; idx < 64 * 128; idx += 256) {
            int s = idx >> 7, c = idx & 127;
            Ks[s * KSTR + c] = f2tf(vc[(sb + s) * (KH * HD) + kvh * HD + c]);
        }

        {
            int r = tid >> 2;
            int qq = tid & 3;
            float* row = Ss + r * SSTR + qq * 16;
            float mold = m_s[r];
            float rmax = -3.0e38f;
            #pragma unroll
            for (int c = 0; c < 16; c++) rmax = fmaxf(rmax, row[c]);
            rmax = fmaxf(rmax, __shfl_xor_sync(0xffffffffu, rmax, 1));
            rmax = fmaxf(rmax, __shfl_xor_sync(0xffffffffu, rmax, 2));
            float mn = fmaxf(mold, rmax);
            float sum = 0.0f;
            #pragma unroll
            for (int c = 0; c < 16; c++) {
                float pv = __expf(row[c] - mn);
                sum += pv;
                row[c] = __uint_as_float(f2tf(pv));
            }
            sum += __shfl_xor_sync(0xffffffffu, sum, 1);
            sum += __shfl_xor_sync(0xffffffffu, sum, 2);
            if (qq == 0) {
                float al = __expf(mold - mn);
                l_s[r] = l_s[r] * al + sum;
                m_s[r] = mn;
                a_s[r] = al;
            }
        }
        __syncthreads();

        const float al0 = a_s[wm + g];
        const float al1 = a_s[wm + g + 8];
        #pragma unroll
        for (int tn = 0; tn < 8; tn++) {
            accO[tn][0] *= al0; accO[tn][1] *= al0;
            accO[tn][2] *= al1; accO[tn][3] *= al1;
        }
        const uint32_t* Ps = (const uint32_t*)Ss;
        #pragma unroll
        for (int ks = 0; ks < 8; ks++) {
            const int k0 = ks * 8;
            uint32_t afr[4], bfr[8][2];
            afr[0] = Ps[(wm + g)     * SSTR + k0 + t];
            afr[1] = Ps[(wm + g + 8) * SSTR + k0 + t];
            afr[2] = Ps[(wm + g)     * SSTR + k0 + t + 4];
            afr[3] = Ps[(wm + g + 8) * SSTR + k0 + t + 4];
            #pragma unroll
            for (int tn = 0; tn < 8; tn++) {
                const int hb = wn * 64 + tn * 8 + g;
                bfr[tn][0] = Ks[(k0 + t)     * KSTR + hb];
                bfr[tn][1] = Ks[(k0 + t + 4) * KSTR + hb];
            }
            #pragma unroll
            for (int tn = 0; tn < 8; tn++) mma8(accO[tn], afr, bfr[tn]);
        }
    }

    // epilogue: 1/l scaling + fused sigmoid gate
    const float inv0 = 1.0f / l_s[wm + g];
    const float inv1 = 1.0f / l_s[wm + g + 8];
    const int row0 = qbase + wm + g;
    const int row1 = row0 + 8;
    #pragma unroll
    for (int tn = 0; tn < 8; tn++) {
        const int cc = wn * 64 + tn * 8 + 2 * t;
        float2 gg0 = *(const float2*)&qg[row0 * (NH * 256) + n * 256 + 128 + cc];
        float2 gg1 = *(const float2*)&qg[row1 * (NH * 256) + n * 256 + 128 + cc];
        float s00 = 1.0f / (1.0f + __expf(-gg0.x));
        float s01 = 1.0f / (1.0f + __expf(-gg0.y));
        float s10 = 1.0f / (1.0f + __expf(-gg1.x));
        float s11 = 1.0f / (1.0f + __expf(-gg1.y));
        float* d0 = enc + row0 * (NH * HD) + n * HD + cc;
        float* d1 = enc + row1 * (NH * HD) + n * HD + cc;
        *(float2*)d0 = make_float2(accO[tn][0] * inv0 * s00, accO[tn][1] * inv0 * s01);
        *(float2*)d1 = make_float2(accO[tn][2] * inv1 * s10, accO[tn][3] * inv1 * s11);
    }
}

// ---------------------------------------------------------------------------
extern "C" void kernel_launch(void* const* d_in, const int* in_sizes, int n_in,
                              void* d_out, int out_size)
{
    const float* x0    = (const float*)d_in[0];
    const float* x1    = (const float*)d_in[1];
    const int*   pos   = (const int*)d_in[2];
    const float* qg_w0 = (const float*)d_in[4];
    const float* k_w0  = (const float*)d_in[5];
    const float* v_w0  = (const float*)d_in[6];
    const float* qn0   = (const float*)d_in[7];
    const float* kn0   = (const float*)d_in[8];
    const float* o_w0  = (const float*)d_in[9];
    const float* qg_w1 = (const float*)d_in[10];
    const float* k_w1  = (const float*)d_in[11];
    const float* v_w1  = (const float*)d_in[12];
    const float* qn1   = (const float*)d_in[13];
    const float* kn1   = (const float*)d_in[14];
    const float* o_w1  = (const float*)d_in[15];

    float* out = (float*)d_out;

    float *qg, *kraw, *q, *enc;
    cudaGetSymbolAddress((void**)&qg,   g_qg);
    cudaGetSymbolAddress((void**)&kraw, g_kraw);
    cudaGetSymbolAddress((void**)&q,    g_q);
    cudaGetSymbolAddress((void**)&enc,  g_enc);

    cudaFuncSetAttribute(proj_fused_kernel, cudaFuncAttributeMaxDynamicSharedMemorySize, GEMM_SMEM_BYTES);
    cudaFuncSetAttribute(proj_out_kernel,   cudaFuncAttributeMaxDynamicSharedMemorySize, GEMM_SMEM_BYTES);
    cudaFuncSetAttribute(attn_kernel, cudaFuncAttributeMaxDynamicSharedMemorySize,
                         ATT_SMEM * sizeof(uint32_t));

    // all projections in one launch (cp.async pipelined tf32 MMA)
    proj_fused_kernel<<<dim3(16, 40), 256, GEMM_SMEM_BYTES>>>(
        x0, x1, qg_w0, qg_w1, k_w0, k_w1, v_w0, v_w1, qg, kraw, out + VC_BASE);

    // norms + rope
    qnorm_rope<<<TT*NH/4, 128>>>(qg, q, pos, qn0, qn1);
    knorm_rope<<<TT*KH/4, 128>>>(kraw, out + KC_BASE, pos, kn0, kn1);

    // attention with fused gate
    attn_kernel<<<dim3(TT/64, NH), 256, ATT_SMEM * sizeof(uint32_t)>>>(
        q, out + KC_BASE, out + VC_BASE, qg, enc);

    // output projection
    proj_out_kernel<<<dim3(16, 16), 256, GEMM_SMEM_BYTES>>>(enc, o_w0, o_w1, out);
}

// round 6
// speedup vs baseline: 4.3735x; 1.1679x over previous
#include <cuda_runtime.h>
#include <cuda_bf16.h>
#include <math.h>
#include <stdint.h>

// Problem constants
#define T0 512
#define TT 2048
#define WIDTH 2048
#define NH 16
#define KH 4
#define HD 128
#define KC_BASE (TT*WIDTH)
#define VC_BASE (KC_BASE + TT*KH*HD)
#define NEGV -2.3819763e38f

// Scratch
__device__ float g_qg[TT * NH * 256];
__device__ float g_kraw[TT * KH * HD];
__device__ float g_q[TT * NH * HD];
__device__ float g_enc[TT * NH * HD];

// ---------------------------------------------------------------------------
// helpers
// ---------------------------------------------------------------------------
__device__ __forceinline__ uint32_t f2tf(float f) {
    uint32_t r;
    asm("cvt.rna.tf32.f32 %0, %1;" : "=r"(r) : "f"(f));
    return r;
}

__device__ __forceinline__ uint32_t smem_u32(const void* p) {
    uint32_t a;
    asm("{ .reg .u64 t; cvta.to.shared.u64 t, %1; cvt.u32.u64 %0, t; }"
        : "=r"(a) : "l"(p));
    return a;
}

__device__ __forceinline__ void cpasync16(uint32_t s, const float* g) {
    asm volatile("cp.async.ca.shared.global [%0], [%1], 16;" :: "r"(s), "l"(g));
}

// m16n8k8 tf32 MMA, fp32 accumulate.
__device__ __forceinline__ void mma8(float* c, const uint32_t* a, const uint32_t* b) {
    asm volatile(
        "mma.sync.aligned.m16n8k8.row.col.f32.tf32.tf32.f32 "
        "{%0,%1,%2,%3},{%4,%5,%6,%7},{%8,%9},{%0,%1,%2,%3};"
        : "+f"(c[0]), "+f"(c[1]), "+f"(c[2]), "+f"(c[3])
        : "r"(a[0]), "r"(a[1]), "r"(a[2]), "r"(a[3]), "r"(b[0]), "r"(b[1]));
}

// ---------------------------------------------------------------------------
// cp.async pipelined tf32 GEMM core (unchanged from Round 5).
// ---------------------------------------------------------------------------
#define ASTRF 20
#define BSTRF 136
#define A_STAGE (128 * ASTRF)
#define B_STAGE (16 * BSTRF)
#define STAGE_F (A_STAGE + B_STAGE)
#define NSTAGE 3
#define GEMM_SMEM_BYTES (NSTAGE * STAGE_F * 4)

__device__ __forceinline__ void issue_stage(
    uint32_t sbase, int stage, const float* A, int lda,
    const float* B, int ldb, int k0, int tid)
{
    const uint32_t aS = sbase + stage * (STAGE_F * 4);
    const uint32_t bS = aS + A_STAGE * 4;
    const int ar = tid >> 2, ak = (tid & 3) * 4;
    const int br = tid >> 5, bc = (tid & 31) * 4;
    cpasync16(aS + (ar * ASTRF + ak) * 4,          A + (long)ar * lda + k0 + ak);
    cpasync16(aS + ((64 + ar) * ASTRF + ak) * 4,   A + (long)(64 + ar) * lda + k0 + ak);
    cpasync16(bS + (br * BSTRF + bc) * 4,          B + (long)(k0 + br) * ldb + bc);
    cpasync16(bS + ((8 + br) * BSTRF + bc) * 4,    B + (long)(k0 + 8 + br) * ldb + bc);
    asm volatile("cp.async.commit_group;" ::: "memory");
}

__device__ void gemm_async_core(
    const float* __restrict__ A, int lda,
    const float* __restrict__ B, int ldb,
    float* __restrict__ C, int ldc, int Kdim)
{
    extern __shared__ float smf[];
    const uint32_t sbase = smem_u32(smf);

    const int tid = threadIdx.x;
    const int lane = tid & 31;
    const int g = lane >> 2;
    const int t = lane & 3;
    const int wid = tid >> 5;
    const int mw = (wid >> 1) * 32;
    const int nw = (wid & 1) * 64;

    const int nt = Kdim / 16;

    issue_stage(sbase, 0, A, lda, B, ldb, 0, tid);
    issue_stage(sbase, 1, A, lda, B, ldb, 16, tid);

    float acc[2][8][4] = {};

    for (int kt = 0; kt < nt; kt++) {
        if (kt + 2 < nt) {
            issue_stage(sbase, (kt + 2) % 3, A, lda, B, ldb, (kt + 2) * 16, tid);
            asm volatile("cp.async.wait_group %0;" :: "n"(2) : "memory");
        } else if (kt + 1 < nt) {
            asm volatile("cp.async.wait_group %0;" :: "n"(1) : "memory");
        } else {
            asm volatile("cp.async.wait_group %0;" :: "n"(0) : "memory");
        }
        __syncthreads();

        const float* AsF = smf + (kt % 3) * STAGE_F;
        const float* BsF = AsF + A_STAGE;

        #pragma unroll
        for (int h = 0; h < 2; h++) {
            const int k0 = h * 8;
            uint32_t afr[2][4], bfr[8][2];
            #pragma unroll
            for (int tm = 0; tm < 2; tm++) {
                const int mb = mw + tm * 16;
                afr[tm][0] = f2tf(AsF[(mb + g)     * ASTRF + k0 + t]);
                afr[tm][1] = f2tf(AsF[(mb + g + 8) * ASTRF + k0 + t]);
                afr[tm][2] = f2tf(AsF[(mb + g)     * ASTRF + k0 + t + 4]);
                afr[tm][3] = f2tf(AsF[(mb + g + 8) * ASTRF + k0 + t + 4]);
            }
            #pragma unroll
            for (int tn = 0; tn < 8; tn++) {
                const int nb = nw + tn * 8 + g;
                bfr[tn][0] = f2tf(BsF[(k0 + t)     * BSTRF + nb]);
                bfr[tn][1] = f2tf(BsF[(k0 + t + 4) * BSTRF + nb]);
            }
            #pragma unroll
            for (int tm = 0; tm < 2; tm++)
                #pragma unroll
                for (int tn = 0; tn < 8; tn++)
                    mma8(acc[tm][tn], afr[tm], bfr[tn]);
        }
        __syncthreads();
    }

    #pragma unroll
    for (int tm = 0; tm < 2; tm++) {
        #pragma unroll
        for (int tn = 0; tn < 8; tn++) {
            const int r0 = mw + tm * 16 + g;
            const int cc = nw + tn * 8 + 2 * t;
            *(float2*)&C[r0 * ldc + cc]       = make_float2(acc[tm][tn][0], acc[tm][tn][1]);
            *(float2*)&C[(r0 + 8) * ldc + cc] = make_float2(acc[tm][tn][2], acc[tm][tn][3]);
        }
    }
}

// Fused projections: qg (y 0..31), K (y 32..35), V (y 36..39). grid (16, 40).
__global__ __launch_bounds__(256, 2) void proj_fused_kernel(
    const float* __restrict__ x0, const float* __restrict__ x1,
    const float* __restrict__ qgw0, const float* __restrict__ qgw1,
    const float* __restrict__ kw0, const float* __restrict__ kw1,
    const float* __restrict__ vw0, const float* __restrict__ vw1,
    float* __restrict__ qg, float* __restrict__ kraw, float* __restrict__ vcache)
{
    const int tile = blockIdx.x;
    const int y = blockIdx.y;
    const float* A = (tile < 4) ? (x0 + (long)tile * 128 * WIDTH)
                                : (x1 + (long)(tile - 4) * 128 * WIDTH);
    const float* B;
    float* C;
    int ldb, ldc;
    if (y < 32) {
        const int n = y >> 1, bn = (y & 1) * 128;
        B = ((tile < 4) ? qgw0 : qgw1) + (long)n * WIDTH * 256 + bn;
        ldb = 256;
        C = qg + (long)tile * 128 * (NH * 256) + n * 256 + bn;
        ldc = NH * 256;
    } else if (y < 36) {
        const int kk = y - 32;
        B = ((tile < 4) ? kw0 : kw1) + (long)kk * WIDTH * HD;
        ldb = HD;
        C = kraw + (long)tile * 128 * (KH * HD) + kk * HD;
        ldc = KH * HD;
    } else {
        const int kk = y - 36;
        B = ((tile < 4) ? vw0 : vw1) + (long)kk * WIDTH * HD;
        ldb = HD;
        C = vcache + (long)tile * 128 * (KH * HD) + kk * HD;
        ldc = KH * HD;
    }
    gemm_async_core(A, WIDTH, B, ldb, C, ldc, WIDTH);
}

// output projection: grid (16, 16)
__global__ __launch_bounds__(256, 2) void proj_out_kernel(
    const float* __restrict__ enc,
    const float* __restrict__ ow0, const float* __restrict__ ow1,
    float* __restrict__ out)
{
    const int tile = blockIdx.x;
    const int bn = blockIdx.y * 128;
    const float* A = enc + (long)tile * 128 * (NH * HD);
    const float* B = ((tile < 4) ? ow0 : ow1) + bn;
    float* C = out + (long)tile * 128 * WIDTH + bn;
    gemm_async_core(A, NH * HD, B, WIDTH, C, WIDTH, NH * HD);
}

// ---------------------------------------------------------------------------
// RMSNorm + RoPE
// ---------------------------------------------------------------------------
__global__ __launch_bounds__(128) void qnorm_rope(
    const float* __restrict__ qg, float* __restrict__ qout,
    const int* __restrict__ positions,
    const float* __restrict__ qn0, const float* __restrict__ qn1)
{
    int row  = blockIdx.x * 4 + (threadIdx.x >> 5);
    int lane = threadIdx.x & 31;
    int t = row >> 4;
    int n = row & 15;
    const float* src = qg + t * (NH * 256) + n * 256;

    float v0 = src[lane];
    float v1 = src[lane + 32];
    float v2 = src[lane + 64];
    float v3 = src[lane + 96];
    float ss = v0 * v0 + v1 * v1 + v2 * v2 + v3 * v3;
    #pragma unroll
    for (int o = 16; o; o >>= 1) ss += __shfl_xor_sync(0xffffffffu, ss, o);
    float inv = rsqrtf(ss * (1.0f / 128.0f) + 1e-6f);

    const float* qn = (t < T0) ? qn0 : qn1;
    v0 = v0 * inv * (1.0f + qn[lane]);
    v1 = v1 * inv * (1.0f + qn[lane + 32]);
    v2 = v2 * inv * (1.0f + qn[lane + 64]);
    v3 = v3 * inv * (1.0f + qn[lane + 96]);

    float p = (float)positions[t];
    float freq = powf(1000000.0f, -(float)lane / 32.0f);
    float s, c;
    sincosf(p * freq, &s, &c);

    const float SCL = 0.08838834764831845f;
    float* dst = qout + t * (NH * HD) + n * HD;
    dst[lane]      = (v0 * c - v1 * s) * SCL;
    dst[lane + 32] = (v1 * c + v0 * s) * SCL;
    dst[lane + 64] = v2 * SCL;
    dst[lane + 96] = v3 * SCL;
}

__global__ __launch_bounds__(128) void knorm_rope(
    const float* __restrict__ kraw, float* __restrict__ kcache,
    const int* __restrict__ positions,
    const float* __restrict__ kn0, const float* __restrict__ kn1)
{
    int row  = blockIdx.x * 4 + (threadIdx.x >> 5);
    int lane = threadIdx.x & 31;
    int t  = row >> 2;
    int kk = row & 3;
    const float* src = kraw + t * (KH * HD) + kk * HD;

    float v0 = src[lane];
    float v1 = src[lane + 32];
    float v2 = src[lane + 64];
    float v3 = src[lane + 96];
    float ss = v0 * v0 + v1 * v1 + v2 * v2 + v3 * v3;
    #pragma unroll
    for (int o = 16; o; o >>= 1) ss += __shfl_xor_sync(0xffffffffu, ss, o);
    float inv = rsqrtf(ss * (1.0f / 128.0f) + 1e-6f);

    const float* kn = (t < T0) ? kn0 : kn1;
    v0 = v0 * inv * (1.0f + kn[lane]);
    v1 = v1 * inv * (1.0f + kn[lane + 32]);
    v2 = v2 * inv * (1.0f + kn[lane + 64]);
    v3 = v3 * inv * (1.0f + kn[lane + 96]);

    float p = (float)positions[t];
    float freq = powf(1000000.0f, -(float)lane / 32.0f);
    float s, c;
    sincosf(p * freq, &s, &c);

    float* dst = kcache + t * (KH * HD) + kk * HD;
    dst[lane]      = v0 * c - v1 * s;
    dst[lane + 32] = v1 * c + v0 * s;
    dst[lane + 64] = v2;
    dst[lane + 96] = v3;
}

// ---------------------------------------------------------------------------
// Flash attention, tf32 mma.sync, 3-slot rotating cp.async K/V pipeline.
// Block = (64-query tile, head), 256 threads, occ 1.
// smem (floats): Q tf32 [64][132] | 3 x KV fp32 [64][132] | S [64][72]
// ---------------------------------------------------------------------------
#define QSTR 132
#define KVSTR 132
#define SSTR 72
#define SLOT_F (64 * KVSTR)
#define AQ_OFF 0
#define AKV_OFF (64 * QSTR)
#define AS_OFF (AKV_OFF + 3 * SLOT_F)
#define ATT_SMEM_F (AS_OFF + 64 * SSTR)

__device__ __forceinline__ void att_issue(
    uint32_t kvbase, int slot, const float* __restrict__ src, int sb, int tid)
{
    const uint32_t dst = kvbase + slot * (SLOT_F * 4);
    #pragma unroll
    for (int i = 0; i < 8; i++) {
        const int lin = tid + 256 * i;
        const int r = lin >> 5;
        const int c4 = (lin & 31) * 4;
        cpasync16(dst + (r * KVSTR + c4) * 4, src + (long)(sb + r) * (KH * HD) + c4);
    }
    asm volatile("cp.async.commit_group;" ::: "memory");
}

__global__ __launch_bounds__(256, 1) void attn_kernel(
    const float* __restrict__ q, const float* __restrict__ kc,
    const float* __restrict__ vc, const float* __restrict__ qg,
    float* __restrict__ enc)
{
    extern __shared__ float smf[];
    uint32_t* Qs = (uint32_t*)(smf + AQ_OFF);
    float*    Ss = smf + AS_OFF;
    const uint32_t kvbase = smem_u32(smf + AKV_OFF);
    __shared__ float m_s[64], l_s[64], a_s[64];

    const int tid = threadIdx.x;
    const int lane = tid & 31;
    const int g = lane >> 2;
    const int t = lane & 3;
    const int wid = tid >> 5;
    const int wm = (wid >> 1) * 16;
    const int wn = wid & 1;
    const int qt = gridDim.x - 1 - blockIdx.x;   // heavy tiles first
    const int n  = blockIdx.y;
    const int kvh = n >> 2;
    const int qbase = qt * 64;

    const float* kbase = kc + kvh * HD;
    const float* vbase = vc + kvh * HD;

    // preamble: stage Q (tf32) and kick off K(0), V(0)
    att_issue(kvbase, 0, kbase, 0, tid);
    att_issue(kvbase, 1, vbase, 0, tid);
    for (int idx = tid; idx < 64 * 128; idx += 256) {
        int r = idx >> 7, c = idx & 127;
        Qs[r * QSTR + c] = f2tf(q[(qbase + r) * (NH * HD) + n * HD + c]);
    }
    if (tid < 64) { m_s[tid] = -3.0e38f; l_s[tid] = 0.0f; }

    float accO[8][4] = {};

    for (int j = 0; j <= qt; j++) {
        const int nsb = (j + 1 <= qt) ? (j + 1) * 64 : qt * 64;  // clamped prefetch

        // K(j) ready (V(j) may still be in flight)
        asm volatile("cp.async.wait_group %0;" :: "n"(1) : "memory");
        __syncthreads();

        // prefetch K(j+1) into slot (2j+2)%3 (freed by PV(j-1))
        att_issue(kvbase, (2 * j + 2) % 3, kbase, nsb, tid);

        // ---- S = Q K^T from slot (2j)%3 ----
        const float* Kf = smf + AKV_OFF + ((2 * j) % 3) * SLOT_F;
        float sacc[4][4] = {};
        #pragma unroll
        for (int ks = 0; ks < 16; ks++) {
            const int k0 = ks * 8;
            uint32_t afr[4], bfr[4][2];
            afr[0] = Qs[(wm + g)     * QSTR + k0 + t];
            afr[1] = Qs[(wm + g + 8) * QSTR + k0 + t];
            afr[2] = Qs[(wm + g)     * QSTR + k0 + t + 4];
            afr[3] = Qs[(wm + g + 8) * QSTR + k0 + t + 4];
            #pragma unroll
            for (int tn = 0; tn < 4; tn++) {
                const int key = wn * 32 + tn * 8 + g;
                bfr[tn][0] = f2tf(Kf[key * KVSTR + k0 + t]);
                bfr[tn][1] = f2tf(Kf[key * KVSTR + k0 + t + 4]);
            }
            #pragma unroll
            for (int tn = 0; tn < 4; tn++) mma8(sacc[tn], afr, bfr[tn]);
        }
        const bool diag = (j == qt);
        #pragma unroll
        for (int tn = 0; tn < 4; tn++) {
            const int cc = wn * 32 + tn * 8 + 2 * t;
            const int r0 = wm + g, r1 = wm + g + 8;
            float v0 = sacc[tn][0], v1 = sacc[tn][1];
            float v2 = sacc[tn][2], v3 = sacc[tn][3];
            if (diag) {
                if (cc     > r0) v0 = NEGV;
                if (cc + 1 > r0) v1 = NEGV;
                if (cc     > r1) v2 = NEGV;
                if (cc + 1 > r1) v3 = NEGV;
            }
            Ss[r0 * SSTR + cc] = v0; Ss[r0 * SSTR + cc + 1] = v1;
            Ss[r1 * SSTR + cc] = v2; Ss[r1 * SSTR + cc + 1] = v3;
        }
        __syncthreads();   // S visible; K(j) slot now free

        // prefetch V(j+1) into K(j)'s slot
        att_issue(kvbase, (2 * j) % 3, vbase, nsb, tid);

        // V(j) ready (K(j+1), V(j+1) may be in flight)
        asm volatile("cp.async.wait_group %0;" :: "n"(2) : "memory");
        __syncthreads();

        // ---- online softmax; store P tf32 ----
        {
            int r = tid >> 2;
            int qq = tid & 3;
            float* row = Ss + r * SSTR + qq * 16;
            float mold = m_s[r];
            float rmax = -3.0e38f;
            #pragma unroll
            for (int c = 0; c < 16; c++) rmax = fmaxf(rmax, row[c]);
            rmax = fmaxf(rmax, __shfl_xor_sync(0xffffffffu, rmax, 1));
            rmax = fmaxf(rmax, __shfl_xor_sync(0xffffffffu, rmax, 2));
            float mn = fmaxf(mold, rmax);
            float sum = 0.0f;
            #pragma unroll
            for (int c = 0; c < 16; c++) {
                float pv = __expf(row[c] - mn);
                sum += pv;
                row[c] = __uint_as_float(f2tf(pv));
            }
            sum += __shfl_xor_sync(0xffffffffu, sum, 1);
            sum += __shfl_xor_sync(0xffffffffu, sum, 2);
            if (qq == 0) {
                float al = __expf(mold - mn);
                l_s[r] = l_s[r] * al + sum;
                m_s[r] = mn;
                a_s[r] = al;
            }
        }
        __syncthreads();

        // ---- rescale + O += P V from slot (2j+1)%3 ----
        const float* Vf = smf + AKV_OFF + ((2 * j + 1) % 3) * SLOT_F;
        const float al0 = a_s[wm + g];
        const float al1 = a_s[wm + g + 8];
        #pragma unroll
        for (int tn = 0; tn < 8; tn++) {
            accO[tn][0] *= al0; accO[tn][1] *= al0;
            accO[tn][2] *= al1; accO[tn][3] *= al1;
        }
        const uint32_t* Ps = (const uint32_t*)Ss;
        #pragma unroll
        for (int ks = 0; ks < 8; ks++) {
            const int k0 = ks * 8;
            uint32_t afr[4], bfr[8][2];
            afr[0] = Ps[(wm + g)     * SSTR + k0 + t];
            afr[1] = Ps[(wm + g + 8) * SSTR + k0 + t];
            afr[2] = Ps[(wm + g)     * SSTR + k0 + t + 4];
            afr[3] = Ps[(wm + g + 8) * SSTR + k0 + t + 4];
            #pragma unroll
            for (int tn = 0; tn < 8; tn++) {
                const int hb = wn * 64 + tn * 8 + g;
                bfr[tn][0] = f2tf(Vf[(k0 + t)     * KVSTR + hb]);
                bfr[tn][1] = f2tf(Vf[(k0 + t + 4) * KVSTR + hb]);
            }
            #pragma unroll
            for (int tn = 0; tn < 8; tn++) mma8(accO[tn], afr, bfr[tn]);
        }
    }

    asm volatile("cp.async.wait_group %0;" :: "n"(0) : "memory");

    // epilogue: 1/l scaling + fused sigmoid gate
    const float inv0 = 1.0f / l_s[wm + g];
    const float inv1 = 1.0f / l_s[wm + g + 8];
    const int row0 = qbase + wm + g;
    const int row1 = row0 + 8;
    #pragma unroll
    for (int tn = 0; tn < 8; tn++) {
        const int cc = wn * 64 + tn * 8 + 2 * t;
        float2 gg0 = *(const float2*)&qg[row0 * (NH * 256) + n * 256 + 128 + cc];
        float2 gg1 = *(const float2*)&qg[row1 * (NH * 256) + n * 256 + 128 + cc];
        float s00 = 1.0f / (1.0f + __expf(-gg0.x));
        float s01 = 1.0f / (1.0f + __expf(-gg0.y));
        float s10 = 1.0f / (1.0f + __expf(-gg1.x));
        float s11 = 1.0f / (1.0f + __expf(-gg1.y));
        float* d0 = enc + row0 * (NH * HD) + n * HD + cc;
        float* d1 = enc + row1 * (NH * HD) + n * HD + cc;
        *(float2*)d0 = make_float2(accO[tn][0] * inv0 * s00, accO[tn][1] * inv0 * s01);
        *(float2*)d1 = make_float2(accO[tn][2] * inv1 * s10, accO[tn][3] * inv1 * s11);
    }
}

// ---------------------------------------------------------------------------
extern "C" void kernel_launch(void* const* d_in, const int* in_sizes, int n_in,
                              void* d_out, int out_size)
{
    const float* x0    = (const float*)d_in[0];
    const float* x1    = (const float*)d_in[1];
    const int*   pos   = (const int*)d_in[2];
    const float* qg_w0 = (const float*)d_in[4];
    const float* k_w0  = (const float*)d_in[5];
    const float* v_w0  = (const float*)d_in[6];
    const float* qn0   = (const float*)d_in[7];
    const float* kn0   = (const float*)d_in[8];
    const float* o_w0  = (const float*)d_in[9];
    const float* qg_w1 = (const float*)d_in[10];
    const float* k_w1  = (const float*)d_in[11];
    const float* v_w1  = (const float*)d_in[12];
    const float* qn1   = (const float*)d_in[13];
    const float* kn1   = (const float*)d_in[14];
    const float* o_w1  = (const float*)d_in[15];

    float* out = (float*)d_out;

    float *qg, *kraw, *q, *enc;
    cudaGetSymbolAddress((void**)&qg,   g_qg);
    cudaGetSymbolAddress((void**)&kraw, g_kraw);
    cudaGetSymbolAddress((void**)&q,    g_q);
    cudaGetSymbolAddress((void**)&enc,  g_enc);

    cudaFuncSetAttribute(proj_fused_kernel, cudaFuncAttributeMaxDynamicSharedMemorySize, GEMM_SMEM_BYTES);
    cudaFuncSetAttribute(proj_out_kernel,   cudaFuncAttributeMaxDynamicSharedMemorySize, GEMM_SMEM_BYTES);
    cudaFuncSetAttribute(attn_kernel, cudaFuncAttributeMaxDynamicSharedMemorySize,
                         ATT_SMEM_F * sizeof(float));

    // all projections in one launch
    proj_fused_kernel<<<dim3(16, 40), 256, GEMM_SMEM_BYTES>>>(
        x0, x1, qg_w0, qg_w1, k_w0, k_w1, v_w0, v_w1, qg, kraw, out + VC_BASE);

    // norms + rope
    qnorm_rope<<<TT*NH/4, 128>>>(qg, q, pos, qn0, qn1);
    knorm_rope<<<TT*KH/4, 128>>>(kraw, out + KC_BASE, pos, kn0, kn1);

    // attention with cp.async pipeline + fused gate
    attn_kernel<<<dim3(TT/64, NH), 256, ATT_SMEM_F * sizeof(float)>>>(
        q, out + KC_BASE, out + VC_BASE, qg, enc);

    // output projection
    proj_out_kernel<<<dim3(16, 16), 256, GEMM_SMEM_BYTES>>>(enc, o_w0, o_w1, out);
}

// round 7
// speedup vs baseline: 4.4711x; 1.0223x over previous
#include <cuda_runtime.h>
#include <cuda_bf16.h>
#include <math.h>
#include <stdint.h>

// Problem constants
#define T0 512
#define TT 2048
#define WIDTH 2048
#define NH 16
#define KH 4
#define HD 128
#define KC_BASE (TT*WIDTH)
#define VC_BASE (KC_BASE + TT*KH*HD)
#define NEGV -2.3819763e38f

// Scratch
__device__ float g_qg[TT * NH * 256];
__device__ float g_kraw[TT * KH * HD];
__device__ float g_q[TT * NH * HD];
__device__ float g_enc[TT * NH * HD];

// ---------------------------------------------------------------------------
// helpers
// ---------------------------------------------------------------------------
__device__ __forceinline__ uint32_t f2tf(float f) {
    uint32_t r;
    asm("cvt.rna.tf32.f32 %0, %1;" : "=r"(r) : "f"(f));
    return r;
}

__device__ __forceinline__ uint32_t smem_u32(const void* p) {
    uint32_t a;
    asm("{ .reg .u64 t; cvta.to.shared.u64 t, %1; cvt.u32.u64 %0, t; }"
        : "=r"(a) : "l"(p));
    return a;
}

__device__ __forceinline__ void cpasync16(uint32_t s, const float* g) {
    asm volatile("cp.async.ca.shared.global [%0], [%1], 16;" :: "r"(s), "l"(g));
}

// m16n8k8 tf32 MMA, fp32 accumulate.
__device__ __forceinline__ void mma8(float* c, const uint32_t* a, const uint32_t* b) {
    asm volatile(
        "mma.sync.aligned.m16n8k8.row.col.f32.tf32.tf32.f32 "
        "{%0,%1,%2,%3},{%4,%5,%6,%7},{%8,%9},{%0,%1,%2,%3};"
        : "+f"(c[0]), "+f"(c[1]), "+f"(c[2]), "+f"(c[3])
        : "r"(a[0]), "r"(a[1]), "r"(a[2]), "r"(a[3]), "r"(b[0]), "r"(b[1]));
}

// ---------------------------------------------------------------------------
// cp.async pipelined tf32 GEMM core (unchanged).
// ---------------------------------------------------------------------------
#define ASTRF 20
#define BSTRF 136
#define A_STAGE (128 * ASTRF)
#define B_STAGE (16 * BSTRF)
#define STAGE_F (A_STAGE + B_STAGE)
#define GEMM_SMEM_BYTES (3 * STAGE_F * 4)

__device__ __forceinline__ void issue_stage(
    uint32_t sbase, int stage, const float* A, int lda,
    const float* B, int ldb, int k0, int tid)
{
    const uint32_t aS = sbase + stage * (STAGE_F * 4);
    const uint32_t bS = aS + A_STAGE * 4;
    const int ar = tid >> 2, ak = (tid & 3) * 4;
    const int br = tid >> 5, bc = (tid & 31) * 4;
    cpasync16(aS + (ar * ASTRF + ak) * 4,          A + (long)ar * lda + k0 + ak);
    cpasync16(aS + ((64 + ar) * ASTRF + ak) * 4,   A + (long)(64 + ar) * lda + k0 + ak);
    cpasync16(bS + (br * BSTRF + bc) * 4,          B + (long)(k0 + br) * ldb + bc);
    cpasync16(bS + ((8 + br) * BSTRF + bc) * 4,    B + (long)(k0 + 8 + br) * ldb + bc);
    asm volatile("cp.async.commit_group;" ::: "memory");
}

__device__ void gemm_async_core(
    const float* __restrict__ A, int lda,
    const float* __restrict__ B, int ldb,
    float* __restrict__ C, int ldc, int Kdim)
{
    extern __shared__ float smf[];
    const uint32_t sbase = smem_u32(smf);

    const int tid = threadIdx.x;
    const int lane = tid & 31;
    const int g = lane >> 2;
    const int t = lane & 3;
    const int wid = tid >> 5;
    const int mw = (wid >> 1) * 32;
    const int nw = (wid & 1) * 64;

    const int nt = Kdim / 16;

    issue_stage(sbase, 0, A, lda, B, ldb, 0, tid);
    issue_stage(sbase, 1, A, lda, B, ldb, 16, tid);

    float acc[2][8][4] = {};

    for (int kt = 0; kt < nt; kt++) {
        if (kt + 2 < nt) {
            issue_stage(sbase, (kt + 2) % 3, A, lda, B, ldb, (kt + 2) * 16, tid);
            asm volatile("cp.async.wait_group %0;" :: "n"(2) : "memory");
        } else if (kt + 1 < nt) {
            asm volatile("cp.async.wait_group %0;" :: "n"(1) : "memory");
        } else {
            asm volatile("cp.async.wait_group %0;" :: "n"(0) : "memory");
        }
        __syncthreads();

        const float* AsF = smf + (kt % 3) * STAGE_F;
        const float* BsF = AsF + A_STAGE;

        #pragma unroll
        for (int h = 0; h < 2; h++) {
            const int k0 = h * 8;
            uint32_t afr[2][4], bfr[8][2];
            #pragma unroll
            for (int tm = 0; tm < 2; tm++) {
                const int mb = mw + tm * 16;
                afr[tm][0] = f2tf(AsF[(mb + g)     * ASTRF + k0 + t]);
                afr[tm][1] = f2tf(AsF[(mb + g + 8) * ASTRF + k0 + t]);
                afr[tm][2] = f2tf(AsF[(mb + g)     * ASTRF + k0 + t + 4]);
                afr[tm][3] = f2tf(AsF[(mb + g + 8) * ASTRF + k0 + t + 4]);
            }
            #pragma unroll
            for (int tn = 0; tn < 8; tn++) {
                const int nb = nw + tn * 8 + g;
                bfr[tn][0] = f2tf(BsF[(k0 + t)     * BSTRF + nb]);
                bfr[tn][1] = f2tf(BsF[(k0 + t + 4) * BSTRF + nb]);
            }
            #pragma unroll
            for (int tm = 0; tm < 2; tm++)
                #pragma unroll
                for (int tn = 0; tn < 8; tn++)
                    mma8(acc[tm][tn], afr[tm], bfr[tn]);
        }
        __syncthreads();
    }

    #pragma unroll
    for (int tm = 0; tm < 2; tm++) {
        #pragma unroll
        for (int tn = 0; tn < 8; tn++) {
            const int r0 = mw + tm * 16 + g;
            const int cc = nw + tn * 8 + 2 * t;
            *(float2*)&C[r0 * ldc + cc]       = make_float2(acc[tm][tn][0], acc[tm][tn][1]);
            *(float2*)&C[(r0 + 8) * ldc + cc] = make_float2(acc[tm][tn][2], acc[tm][tn][3]);
        }
    }
}

// Fused projections: qg (y 0..31), K (y 32..35), V (y 36..39). grid (16, 40).
__global__ __launch_bounds__(256, 2) void proj_fused_kernel(
    const float* __restrict__ x0, const float* __restrict__ x1,
    const float* __restrict__ qgw0, const float* __restrict__ qgw1,
    const float* __restrict__ kw0, const float* __restrict__ kw1,
    const float* __restrict__ vw0, const float* __restrict__ vw1,
    float* __restrict__ qg, float* __restrict__ kraw, float* __restrict__ vcache)
{
    const int tile = blockIdx.x;
    const int y = blockIdx.y;
    const float* A = (tile < 4) ? (x0 + (long)tile * 128 * WIDTH)
                                : (x1 + (long)(tile - 4) * 128 * WIDTH);
    const float* B;
    float* C;
    int ldb, ldc;
    if (y < 32) {
        const int n = y >> 1, bn = (y & 1) * 128;
        B = ((tile < 4) ? qgw0 : qgw1) + (long)n * WIDTH * 256 + bn;
        ldb = 256;
        C = qg + (long)tile * 128 * (NH * 256) + n * 256 + bn;
        ldc = NH * 256;
    } else if (y < 36) {
        const int kk = y - 32;
        B = ((tile < 4) ? kw0 : kw1) + (long)kk * WIDTH * HD;
        ldb = HD;
        C = kraw + (long)tile * 128 * (KH * HD) + kk * HD;
        ldc = KH * HD;
    } else {
        const int kk = y - 36;
        B = ((tile < 4) ? vw0 : vw1) + (long)kk * WIDTH * HD;
        ldb = HD;
        C = vcache + (long)tile * 128 * (KH * HD) + kk * HD;
        ldc = KH * HD;
    }
    gemm_async_core(A, WIDTH, B, ldb, C, ldc, WIDTH);
}

// output projection: grid (16, 16)
__global__ __launch_bounds__(256, 2) void proj_out_kernel(
    const float* __restrict__ enc,
    const float* __restrict__ ow0, const float* __restrict__ ow1,
    float* __restrict__ out)
{
    const int tile = blockIdx.x;
    const int bn = blockIdx.y * 128;
    const float* A = enc + (long)tile * 128 * (NH * HD);
    const float* B = ((tile < 4) ? ow0 : ow1) + bn;
    float* C = out + (long)tile * 128 * WIDTH + bn;
    gemm_async_core(A, NH * HD, B, WIDTH, C, WIDTH, NH * HD);
}

// ---------------------------------------------------------------------------
// RMSNorm + RoPE
// ---------------------------------------------------------------------------
__global__ __launch_bounds__(128) void qnorm_rope(
    const float* __restrict__ qg, float* __restrict__ qout,
    const int* __restrict__ positions,
    const float* __restrict__ qn0, const float* __restrict__ qn1)
{
    int row  = blockIdx.x * 4 + (threadIdx.x >> 5);
    int lane = threadIdx.x & 31;
    int t = row >> 4;
    int n = row & 15;
    const float* src = qg + t * (NH * 256) + n * 256;

    float v0 = src[lane];
    float v1 = src[lane + 32];
    float v2 = src[lane + 64];
    float v3 = src[lane + 96];
    float ss = v0 * v0 + v1 * v1 + v2 * v2 + v3 * v3;
    #pragma unroll
    for (int o = 16; o; o >>= 1) ss += __shfl_xor_sync(0xffffffffu, ss, o);
    float inv = rsqrtf(ss * (1.0f / 128.0f) + 1e-6f);

    const float* qn = (t < T0) ? qn0 : qn1;
    v0 = v0 * inv * (1.0f + qn[lane]);
    v1 = v1 * inv * (1.0f + qn[lane + 32]);
    v2 = v2 * inv * (1.0f + qn[lane + 64]);
    v3 = v3 * inv * (1.0f + qn[lane + 96]);

    float p = (float)positions[t];
    float freq = powf(1000000.0f, -(float)lane / 32.0f);
    float s, c;
    sincosf(p * freq, &s, &c);

    const float SCL = 0.08838834764831845f;
    float* dst = qout + t * (NH * HD) + n * HD;
    dst[lane]      = (v0 * c - v1 * s) * SCL;
    dst[lane + 32] = (v1 * c + v0 * s) * SCL;
    dst[lane + 64] = v2 * SCL;
    dst[lane + 96] = v3 * SCL;
}

__global__ __launch_bounds__(128) void knorm_rope(
    const float* __restrict__ kraw, float* __restrict__ kcache,
    const int* __restrict__ positions,
    const float* __restrict__ kn0, const float* __restrict__ kn1)
{
    int row  = blockIdx.x * 4 + (threadIdx.x >> 5);
    int lane = threadIdx.x & 31;
    int t  = row >> 2;
    int kk = row & 3;
    const float* src = kraw + t * (KH * HD) + kk * HD;

    float v0 = src[lane];
    float v1 = src[lane + 32];
    float v2 = src[lane + 64];
    float v3 = src[lane + 96];
    float ss = v0 * v0 + v1 * v1 + v2 * v2 + v3 * v3;
    #pragma unroll
    for (int o = 16; o; o >>= 1) ss += __shfl_xor_sync(0xffffffffu, ss, o);
    float inv = rsqrtf(ss * (1.0f / 128.0f) + 1e-6f);

    const float* kn = (t < T0) ? kn0 : kn1;
    v0 = v0 * inv * (1.0f + kn[lane]);
    v1 = v1 * inv * (1.0f + kn[lane + 32]);
    v2 = v2 * inv * (1.0f + kn[lane + 64]);
    v3 = v3 * inv * (1.0f + kn[lane + 96]);

    float p = (float)positions[t];
    float freq = powf(1000000.0f, -(float)lane / 32.0f);
    float s, c;
    sincosf(p * freq, &s, &c);

    float* dst = kcache + t * (KH * HD) + kk * HD;
    dst[lane]      = v0 * c - v1 * s;
    dst[lane + 32] = v1 * c + v0 * s;
    dst[lane + 64] = v2;
    dst[lane + 96] = v3;
}

// ---------------------------------------------------------------------------
// Flash attention: 2 heads (sharing K/V via GQA) x 64 queries per CTA.
// 256 threads, tf32 mma.sync, 3-slot rotating cp.async K/V pipeline.
// Q rows 0..63 = head n0, rows 64..127 = head n0+1 (same query positions,
// same causal mask). S is 128x64.
// smem (floats): Q tf32 [128][132] | 3 x KV fp32 [64][132] | S [128][72]
// ---------------------------------------------------------------------------
#define QSTR 132
#define KVSTR 132
#define SSTR 72
#define SLOT_F (64 * KVSTR)
#define AQ_OFF 0
#define AKV_OFF (128 * QSTR)
#define AS_OFF (AKV_OFF + 3 * SLOT_F)
#define ATT_SMEM_F (AS_OFF + 128 * SSTR)

__device__ __forceinline__ void att_issue(
    uint32_t kvbase, int slot, const float* __restrict__ src, int sb, int tid)
{
    const uint32_t dst = kvbase + slot * (SLOT_F * 4);
    #pragma unroll
    for (int i = 0; i < 8; i++) {
        const int lin = tid + 256 * i;
        const int r = lin >> 5;
        const int c4 = (lin & 31) * 4;
        cpasync16(dst + (r * KVSTR + c4) * 4, src + (long)(sb + r) * (KH * HD) + c4);
    }
    asm volatile("cp.async.commit_group;" ::: "memory");
}

__global__ __launch_bounds__(256, 1) void attn_kernel(
    const float* __restrict__ q, const float* __restrict__ kc,
    const float* __restrict__ vc, const float* __restrict__ qg,
    float* __restrict__ enc)
{
    extern __shared__ float smf[];
    uint32_t* Qs = (uint32_t*)(smf + AQ_OFF);
    float*    Ss = smf + AS_OFF;
    const uint32_t kvbase = smem_u32(smf + AKV_OFF);
    __shared__ float m_s[128], l_s[128], a_s[128];

    const int tid = threadIdx.x;
    const int lane = tid & 31;
    const int g = lane >> 2;
    const int t = lane & 3;
    const int wid = tid >> 5;
    const int wm = (wid >> 1) * 32;  // warp M base (2 m16 tiles)
    const int wn = wid & 1;
    const int qt = gridDim.x - 1 - blockIdx.x;   // heavy tiles first
    const int n0 = blockIdx.y * 2;               // head pair (same kvh)
    const int kvh = n0 >> 2;
    const int qbase = qt * 64;

    const float* kbase = kc + kvh * HD;
    const float* vbase = vc + kvh * HD;

    // preamble: kick off K(0), V(0); stage Q (tf32) for both heads
    att_issue(kvbase, 0, kbase, 0, tid);
    att_issue(kvbase, 1, vbase, 0, tid);
    for (int idx = tid; idx < 128 * 128; idx += 256) {
        int r = idx >> 7, c = idx & 127;
        int head = n0 + (r >> 6);
        int qrow = qbase + (r & 63);
        Qs[r * QSTR + c] = f2tf(q[qrow * (NH * HD) + head * HD + c]);
    }
    if (tid < 128) { m_s[tid] = -3.0e38f; l_s[tid] = 0.0f; }

    float accO[2][8][4] = {};   // [tm][tn][4]

    for (int j = 0; j <= qt; j++) {
        const int nsb = (j + 1 <= qt) ? (j + 1) * 64 : qt * 64;  // clamped prefetch

        // K(j) ready (V(j) may still be in flight)
        asm volatile("cp.async.wait_group %0;" :: "n"(1) : "memory");
        __syncthreads();

        // prefetch K(j+1) into slot freed by PV(j-1)
        att_issue(kvbase, (2 * j + 2) % 3, kbase, nsb, tid);

        // ---- S = Q K^T (128x64) from slot (2j)%3. Warp tile 32x32. ----
        const float* Kf = smf + AKV_OFF + ((2 * j) % 3) * SLOT_F;
        float sacc[2][4][4] = {};
        #pragma unroll
        for (int ks = 0; ks < 16; ks++) {
            const int k0 = ks * 8;
            uint32_t afr[2][4], bfr[4][2];
            #pragma unroll
            for (int tm = 0; tm < 2; tm++) {
                const int mb = wm + tm * 16;
                afr[tm][0] = Qs[(mb + g)     * QSTR + k0 + t];
                afr[tm][1] = Qs[(mb + g + 8) * QSTR + k0 + t];
                afr[tm][2] = Qs[(mb + g)     * QSTR + k0 + t + 4];
                afr[tm][3] = Qs[(mb + g + 8) * QSTR + k0 + t + 4];
            }
            #pragma unroll
            for (int tn = 0; tn < 4; tn++) {
                const int key = wn * 32 + tn * 8 + g;
                bfr[tn][0] = f2tf(Kf[key * KVSTR + k0 + t]);
                bfr[tn][1] = f2tf(Kf[key * KVSTR + k0 + t + 4]);
            }
            #pragma unroll
            for (int tm = 0; tm < 2; tm++)
                #pragma unroll
                for (int tn = 0; tn < 4; tn++)
                    mma8(sacc[tm][tn], afr[tm], bfr[tn]);
        }
        const bool diag = (j == qt);
        #pragma unroll
        for (int tm = 0; tm < 2; tm++) {
            #pragma unroll
            for (int tn = 0; tn < 4; tn++) {
                const int cc = wn * 32 + tn * 8 + 2 * t;
                const int r0 = wm + tm * 16 + g, r1 = r0 + 8;
                const int q0 = r0 & 63, q1 = r1 & 63;   // query row within tile
                float v0 = sacc[tm][tn][0], v1 = sacc[tm][tn][1];
                float v2 = sacc[tm][tn][2], v3 = sacc[tm][tn][3];
                if (diag) {
                    if (cc     > q0) v0 = NEGV;
                    if (cc + 1 > q0) v1 = NEGV;
                    if (cc     > q1) v2 = NEGV;
                    if (cc + 1 > q1) v3 = NEGV;
                }
                Ss[r0 * SSTR + cc] = v0; Ss[r0 * SSTR + cc + 1] = v1;
                Ss[r1 * SSTR + cc] = v2; Ss[r1 * SSTR + cc + 1] = v3;
            }
        }
        __syncthreads();   // S visible; K(j) slot now free

        // prefetch V(j+1) into K(j)'s slot
        att_issue(kvbase, (2 * j) % 3, vbase, nsb, tid);

        // V(j) ready
        asm volatile("cp.async.wait_group %0;" :: "n"(2) : "memory");
        __syncthreads();

        // ---- online softmax: 2 threads per row, 32 cols each ----
        {
            int r = tid >> 1;
            int qq = tid & 1;
            float* row = Ss + r * SSTR + qq * 32;
            float mold = m_s[r];
            float rmax = -3.0e38f;
            #pragma unroll
            for (int c = 0; c < 32; c++) rmax = fmaxf(rmax, row[c]);
            rmax = fmaxf(rmax, __shfl_xor_sync(0xffffffffu, rmax, 1));
            float mn = fmaxf(mold, rmax);
            float sum = 0.0f;
            #pragma unroll
            for (int c = 0; c < 32; c++) {
                float pv = __expf(row[c] - mn);
                sum += pv;
                row[c] = __uint_as_float(f2tf(pv));
            }
            sum += __shfl_xor_sync(0xffffffffu, sum, 1);
            if (qq == 0) {
                float al = __expf(mold - mn);
                l_s[r] = l_s[r] * al + sum;
                m_s[r] = mn;
                a_s[r] = al;
            }
        }
        __syncthreads();

        // ---- rescale + O += P V from slot (2j+1)%3. Warp tile 32x64. ----
        const float* Vf = smf + AKV_OFF + ((2 * j + 1) % 3) * SLOT_F;
        #pragma unroll
        for (int tm = 0; tm < 2; tm++) {
            const float al0 = a_s[wm + tm * 16 + g];
            const float al1 = a_s[wm + tm * 16 + g + 8];
            #pragma unroll
            for (int tn = 0; tn < 8; tn++) {
                accO[tm][tn][0] *= al0; accO[tm][tn][1] *= al0;
                accO[tm][tn][2] *= al1; accO[tm][tn][3] *= al1;
            }
        }
        const uint32_t* Ps = (const uint32_t*)Ss;
        #pragma unroll
        for (int ks = 0; ks < 8; ks++) {
            const int k0 = ks * 8;
            uint32_t afr[2][4], bfr[8][2];
            #pragma unroll
            for (int tm = 0; tm < 2; tm++) {
                const int mb = wm + tm * 16;
                afr[tm][0] = Ps[(mb + g)     * SSTR + k0 + t];
                afr[tm][1] = Ps[(mb + g + 8) * SSTR + k0 + t];
                afr[tm][2] = Ps[(mb + g)     * SSTR + k0 + t + 4];
                afr[tm][3] = Ps[(mb + g + 8) * SSTR + k0 + t + 4];
            }
            #pragma unroll
            for (int tn = 0; tn < 8; tn++) {
                const int hb = wn * 64 + tn * 8 + g;
                bfr[tn][0] = f2tf(Vf[(k0 + t)     * KVSTR + hb]);
                bfr[tn][1] = f2tf(Vf[(k0 + t + 4) * KVSTR + hb]);
            }
            #pragma unroll
            for (int tm = 0; tm < 2; tm++)
                #pragma unroll
                for (int tn = 0; tn < 8; tn++)
                    mma8(accO[tm][tn], afr[tm], bfr[tn]);
        }
    }

    asm volatile("cp.async.wait_group %0;" :: "n"(0) : "memory");

    // epilogue: 1/l scaling + fused sigmoid gate
    #pragma unroll
    for (int tm = 0; tm < 2; tm++) {
        const int r0 = wm + tm * 16 + g;
        const int r1 = r0 + 8;
        const int h0 = n0 + (r0 >> 6), h1 = n0 + (r1 >> 6);
        const int qr0 = qbase + (r0 & 63), qr1 = qbase + (r1 & 63);
        const float inv0 = 1.0f / l_s[r0];
        const float inv1 = 1.0f / l_s[r1];
        #pragma unroll
        for (int tn = 0; tn < 8; tn++) {
            const int cc = wn * 64 + tn * 8 + 2 * t;
            float2 gg0 = *(const float2*)&qg[qr0 * (NH * 256) + h0 * 256 + 128 + cc];
            float2 gg1 = *(const float2*)&qg[qr1 * (NH * 256) + h1 * 256 + 128 + cc];
            float s00 = 1.0f / (1.0f + __expf(-gg0.x));
            float s01 = 1.0f / (1.0f + __expf(-gg0.y));
            float s10 = 1.0f / (1.0f + __expf(-gg1.x));
            float s11 = 1.0f / (1.0f + __expf(-gg1.y));
            float* d0 = enc + qr0 * (NH * HD) + h0 * HD + cc;
            float* d1 = enc + qr1 * (NH * HD) + h1 * HD + cc;
            *(float2*)d0 = make_float2(accO[tm][tn][0] * inv0 * s00, accO[tm][tn][1] * inv0 * s01);
            *(float2*)d1 = make_float2(accO[tm][tn][2] * inv1 * s10, accO[tm][tn][3] * inv1 * s11);
        }
    }
}

// ---------------------------------------------------------------------------
extern "C" void kernel_launch(void* const* d_in, const int* in_sizes, int n_in,
                              void* d_out, int out_size)
{
    const float* x0    = (const float*)d_in[0];
    const float* x1    = (const float*)d_in[1];
    const int*   pos   = (const int*)d_in[2];
    const float* qg_w0 = (const float*)d_in[4];
    const float* k_w0  = (const float*)d_in[5];
    const float* v_w0  = (const float*)d_in[6];
    const float* qn0   = (const float*)d_in[7];
    const float* kn0   = (const float*)d_in[8];
    const float* o_w0  = (const float*)d_in[9];
    const float* qg_w1 = (const float*)d_in[10];
    const float* k_w1  = (const float*)d_in[11];
    const float* v_w1  = (const float*)d_in[12];
    const float* qn1   = (const float*)d_in[13];
    const float* kn1   = (const float*)d_in[14];
    const float* o_w1  = (const float*)d_in[15];

    float* out = (float*)d_out;

    float *qg, *kraw, *q, *enc;
    cudaGetSymbolAddress((void**)&qg,   g_qg);
    cudaGetSymbolAddress((void**)&kraw, g_kraw);
    cudaGetSymbolAddress((void**)&q,    g_q);
    cudaGetSymbolAddress((void**)&enc,  g_enc);

    cudaFuncSetAttribute(proj_fused_kernel, cudaFuncAttributeMaxDynamicSharedMemorySize, GEMM_SMEM_BYTES);
    cudaFuncSetAttribute(proj_out_kernel,   cudaFuncAttributeMaxDynamicSharedMemorySize, GEMM_SMEM_BYTES);
    cudaFuncSetAttribute(attn_kernel, cudaFuncAttributeMaxDynamicSharedMemorySize,
                         ATT_SMEM_F * sizeof(float));

    // all projections in one launch
    proj_fused_kernel<<<dim3(16, 40), 256, GEMM_SMEM_BYTES>>>(
        x0, x1, qg_w0, qg_w1, k_w0, k_w1, v_w0, v_w1, qg, kraw, out + VC_BASE);

    // norms + rope
    qnorm_rope<<<TT*NH/4, 128>>>(qg, q, pos, qn0, qn1);
    knorm_rope<<<TT*KH/4, 128>>>(kraw, out + KC_BASE, pos, kn0, kn1);

    // attention: 2 GQA heads per CTA, cp.async pipeline, fused gate
    attn_kernel<<<dim3(TT/64, NH/2), 256, ATT_SMEM_F * sizeof(float)>>>(
        q, out + KC_BASE, out + VC_BASE, qg, enc);

    // output projection
    proj_out_kernel<<<dim3(16, 16), 256, GEMM_SMEM_BYTES>>>(enc, o_w0, o_w1, out);
}